// round 7
// baseline (speedup 1.0000x reference)
#include <cuda_runtime.h>
#include <math.h>

#define NMAX 50000
#define EMAX 400000

// ---------------- scratch (device globals; no dynamic allocation) ----------------
__device__ float g_h1[(size_t)NMAX * 512];
__device__ float g_o1[(size_t)NMAX * 512];
__device__ float g_h2[(size_t)NMAX * 128];
__device__ float g_o2[(size_t)NMAX * 128];
__device__ float g_h3[NMAX * 8];
__device__ float g_o3[NMAX * 8];
__device__ float g_s[NMAX * 4];
__device__ float g_d[NMAX * 4];
__device__ float g_alpha[(size_t)(EMAX + NMAX) * 4];
__device__ int   g_counts[NMAX];
__device__ int   g_rowptr[NMAX + 1];
__device__ int   g_cursor[NMAX];
__device__ int   g_esrc[EMAX + NMAX];
__device__ int   g_epos[EMAX + NMAX];

// ---------------- CSR construction ----------------
__global__ void k_init_counts(int* counts, int nn) {
    int i = blockIdx.x * blockDim.x + threadIdx.x;
    if (i < nn) counts[i] = 1;   // self-loop per node
}

__global__ void k_count_edges(const int* __restrict__ ei, int* counts, int E) {
    int i = blockIdx.x * blockDim.x + threadIdx.x;
    if (i < E) atomicAdd(&counts[ei[E + i]], 1);
}

__global__ void k_scan(const int* __restrict__ counts, int* rp, int* cur, int nn) {
    __shared__ int part[1024];
    int tid = threadIdx.x;
    int per = (nn + 1023) >> 10;
    int b = tid * per;
    int e = min(b + per, nn);
    int s = 0;
    for (int i = b; i < e; i++) s += counts[i];
    part[tid] = s;
    __syncthreads();
    if (tid == 0) {
        int run = 0;
        for (int i = 0; i < 1024; i++) { int v = part[i]; part[i] = run; run += v; }
    }
    __syncthreads();
    int run = part[tid];
    for (int i = b; i < e; i++) { rp[i] = run; cur[i] = run; run += counts[i]; }
    if (e == nn) rp[nn] = run;
}

__global__ void k_scatter(const int* __restrict__ ei, int* cur, int* esrc, int* epos,
                          int E, int nn) {
    int i = blockIdx.x * blockDim.x + threadIdx.x;
    if (i >= E + nn) return;
    int s, dd;
    if (i < E) { s = ei[i]; dd = ei[E + i]; }
    else       { s = i - E; dd = s; }
    int pos = atomicAdd(&cur[dd], 1);
    esrc[pos] = s;
    epos[i] = pos;
}

// ---------------- TF32 tensor-core GEMM: C[M,N] = A[M,K] @ B[N,K]^T --------------
__device__ __forceinline__ float f2tf32(float x) {
    unsigned u;
    asm("cvt.rna.tf32.f32 %0, %1;" : "=r"(u) : "f"(x));
    return __uint_as_float(u);
}

__global__ __launch_bounds__(256) void mma_nt(
    const float* __restrict__ A, const float* __restrict__ B,
    float* __restrict__ C, int M, int N, int K) {
    __shared__ float As[128][36];
    __shared__ float Bs[128][36];
    const int t = threadIdx.x;
    const int lane = t & 31;
    const int wid = t >> 5;
    const int wm = (wid & 1) * 64;
    const int wn = (wid >> 1) * 32;
    const int group = lane >> 2, tig = lane & 3;
    const int bm = blockIdx.y * 128, bn = blockIdx.x * 128;
    const int lr = t >> 3;
    const int lc = (t & 7) * 4;

    float c[4][4][4];
#pragma unroll
    for (int i = 0; i < 4; i++)
#pragma unroll
        for (int j = 0; j < 4; j++)
#pragma unroll
            for (int q = 0; q < 4; q++) c[i][j][q] = 0.f;

    for (int kk = 0; kk < K; kk += 32) {
#pragma unroll
        for (int i = 0; i < 4; i++) {
            int m = lr + i * 32;
            int gm = bm + m;
            float4 av = make_float4(0.f, 0.f, 0.f, 0.f);
            if (gm < M) av = *(const float4*)(A + (size_t)gm * K + kk + lc);
            As[m][lc + 0] = f2tf32(av.x); As[m][lc + 1] = f2tf32(av.y);
            As[m][lc + 2] = f2tf32(av.z); As[m][lc + 3] = f2tf32(av.w);
            float4 bv = *(const float4*)(B + (size_t)(bn + m) * K + kk + lc);
            Bs[m][lc + 0] = f2tf32(bv.x); Bs[m][lc + 1] = f2tf32(bv.y);
            Bs[m][lc + 2] = f2tf32(bv.z); Bs[m][lc + 3] = f2tf32(bv.w);
        }
        __syncthreads();
#pragma unroll
        for (int ks = 0; ks < 32; ks += 8) {
            unsigned bf[4][2];
#pragma unroll
            for (int nf = 0; nf < 4; nf++) {
                const float* bp = &Bs[wn + nf * 8 + group][ks + tig];
                bf[nf][0] = __float_as_uint(bp[0]);
                bf[nf][1] = __float_as_uint(bp[4]);
            }
#pragma unroll
            for (int mf = 0; mf < 4; mf++) {
                const float* ap0 = &As[wm + mf * 16 + group][ks + tig];
                const float* ap1 = &As[wm + mf * 16 + group + 8][ks + tig];
                unsigned a0 = __float_as_uint(ap0[0]);
                unsigned a1 = __float_as_uint(ap1[0]);
                unsigned a2 = __float_as_uint(ap0[4]);
                unsigned a3 = __float_as_uint(ap1[4]);
#pragma unroll
                for (int nf = 0; nf < 4; nf++) {
                    asm volatile(
                        "mma.sync.aligned.m16n8k8.row.col.f32.tf32.tf32.f32 "
                        "{%0,%1,%2,%3}, {%4,%5,%6,%7}, {%8,%9}, {%0,%1,%2,%3};"
                        : "+f"(c[mf][nf][0]), "+f"(c[mf][nf][1]),
                          "+f"(c[mf][nf][2]), "+f"(c[mf][nf][3])
                        : "r"(a0), "r"(a1), "r"(a2), "r"(a3),
                          "r"(bf[nf][0]), "r"(bf[nf][1]));
                }
            }
        }
        __syncthreads();
    }
#pragma unroll
    for (int mf = 0; mf < 4; mf++) {
        int m0 = bm + wm + mf * 16 + group;
        int m1 = m0 + 8;
#pragma unroll
        for (int nf = 0; nf < 4; nf++) {
            int n0 = bn + wn + nf * 8 + tig * 2;
            if (m0 < M) *(float2*)(C + (size_t)m0 * N + n0) = make_float2(c[mf][nf][0], c[mf][nf][1]);
            if (m1 < M) *(float2*)(C + (size_t)m1 * N + n0) = make_float2(c[mf][nf][2], c[mf][nf][3]);
        }
    }
}

// ---------------- thin GEMM for layer 3: C[M,8] = A[M,128] @ W3[8,128]^T ----------
__global__ void gemm_thin8(const float* __restrict__ A, const float* __restrict__ B,
                           float* __restrict__ C, int M) {
    __shared__ float sB[8 * 128];
    for (int i = threadIdx.x; i < 8 * 128; i += blockDim.x) sB[i] = B[i];
    __syncthreads();
    int idx = blockIdx.x * blockDim.x + threadIdx.x;
    if (idx >= M * 8) return;
    int n = idx >> 3, j = idx & 7;
    const float* a = A + (size_t)n * 128;
    const float* w = sB + j * 128;
    float s = 0.f;
#pragma unroll
    for (int k = 0; k < 128; k += 4) {
        float4 v = *(const float4*)(a + k);
        s += v.x * w[k] + v.y * w[k + 1] + v.z * w[k + 2] + v.w * w[k + 3];
    }
    C[idx] = s;
}

// ---------------- per-node attention logits s,d: warp per (node,head) -------------
template <int H, int C>
__global__ void k_sd_w(const float* __restrict__ h, const float* __restrict__ as,
                       const float* __restrict__ ad, float* __restrict__ s,
                       float* __restrict__ d, int nn) {
    int w = (blockIdx.x * blockDim.x + threadIdx.x) >> 5;
    int lane = threadIdx.x & 31;
    if (w >= nn * H) return;
    int n = w / H, hh = w % H;
    float ss = 0.f, dd = 0.f;
    if (lane * 4 < C) {
        float4 v = *(const float4*)(h + (size_t)n * (H * C) + hh * C + lane * 4);
        float4 a = *(const float4*)(as + hh * C + lane * 4);
        float4 b = *(const float4*)(ad + hh * C + lane * 4);
        ss = v.x * a.x + v.y * a.y + v.z * a.z + v.w * a.w;
        dd = v.x * b.x + v.y * b.y + v.z * b.z + v.w * b.w;
    }
#pragma unroll
    for (int o = 16; o; o >>= 1) {
        ss += __shfl_xor_sync(0xffffffffu, ss, o);
        dd += __shfl_xor_sync(0xffffffffu, dd, o);
    }
    if (lane == 0) { s[w] = ss; d[w] = dd; }
}

// ---------------- edge-parallel unnormalized attention weights -------------------
// alpha[pos*H+h] = exp(leaky_relu(s[src,h] + d[dst,h]))   (no max shift; logits bounded)
template <int H>
__global__ void k_alpha(const float* __restrict__ s, const float* __restrict__ d,
                        const int* __restrict__ ei, const int* __restrict__ epos,
                        float* __restrict__ alpha, int E, int nn) {
    int i = blockIdx.x * blockDim.x + threadIdx.x;
    if (i >= E + nn) return;
    int src, dst;
    if (i < E) { src = ei[i]; dst = ei[E + i]; }
    else       { src = dst = i - E; }
    int pos = epos[i];
#pragma unroll
    for (int h = 0; h < H; h++) {
        float e = s[src * H + h] + d[dst * H + h];
        e = e > 0.f ? e : 0.2f * e;
        alpha[(size_t)pos * H + h] = __expf(e);
    }
}

// ---------------- GAT aggregation (atomic-free, CSR by dst, precomputed alpha) ----
template <int H, int C, int LPN>
__global__ void gat_agg(const float* __restrict__ h, const float* __restrict__ alpha,
                        const float* __restrict__ bias,
                        const int* __restrict__ rp, const int* __restrict__ esrc,
                        float* __restrict__ out, int nn) {
    constexpr int F = H * C;
    constexpr int VPL = F / LPN;
    constexpr int NPW = 32 / LPN;
    int gwarp = (blockIdx.x * blockDim.x + threadIdx.x) >> 5;
    int lane = threadIdx.x & 31;
    int node = gwarp * NPW + lane / LPN;
    if (node >= nn) return;
    int sub = lane % LPN;
    int myh = (sub * VPL) / C;
    int beg = rp[node], end = rp[node + 1];

    float acc[VPL];
#pragma unroll
    for (int j = 0; j < VPL; j++) acc[j] = 0.f;
    float den = 0.f;
#pragma unroll 2
    for (int i = beg; i < end; i++) {
        int sc = esrc[i];
        float w = alpha[(size_t)i * H + myh];
        den += w;
        if constexpr (VPL % 4 == 0) {
            const float4* hp4 = reinterpret_cast<const float4*>(h + (size_t)sc * F + sub * VPL);
#pragma unroll
            for (int j = 0; j < VPL / 4; j++) {
                float4 v = hp4[j];
                acc[4 * j + 0] += w * v.x;
                acc[4 * j + 1] += w * v.y;
                acc[4 * j + 2] += w * v.z;
                acc[4 * j + 3] += w * v.w;
            }
        } else {
            const float* hp = h + (size_t)sc * F + sub * VPL;
#pragma unroll
            for (int j = 0; j < VPL; j++) acc[j] += w * hp[j];
        }
    }
    float inv = 1.f / den;
#pragma unroll
    for (int j = 0; j < VPL; j++) {
        float v = acc[j] * inv + bias[sub * VPL + j];
        out[(size_t)node * F + sub * VPL + j] = v > 0.f ? v : expm1f(v);
    }
}

// ---------------- final edge MLP: 19 -> 16 -> 1 ----------------
__global__ void edge_mlp(const float* __restrict__ h3, const int* __restrict__ ei,
                         const float* __restrict__ ea, const float* __restrict__ yr,
                         const float* __restrict__ qt, const float* __restrict__ w1,
                         const float* __restrict__ b1, const float* __restrict__ w2,
                         const float* __restrict__ b2, float* __restrict__ out, int E) {
    __shared__ float sw1[16 * 19], sb1[16], sw2[16], sb2;
    for (int i = threadIdx.x; i < 16 * 19; i += blockDim.x) sw1[i] = w1[i];
    if (threadIdx.x < 16) { sb1[threadIdx.x] = b1[threadIdx.x]; sw2[threadIdx.x] = w2[threadIdx.x]; }
    if (threadIdx.x == 0) sb2 = b2[0];
    __syncthreads();
    int e = blockIdx.x * blockDim.x + threadIdx.x;
    if (e >= E) return;
    int si = ei[e], di = ei[E + e];
    float z[19];
#pragma unroll
    for (int j = 0; j < 8; j++) { z[j] = h3[si * 8 + j]; z[8 + j] = h3[di * 8 + j]; }
    z[16] = ea[e];
    z[17] = yr[e];
    z[18] = qt[e];
    float o = sb2;
#pragma unroll
    for (int j = 0; j < 16; j++) {
        float a = sb1[j];
#pragma unroll
        for (int i = 0; i < 19; i++) a += sw1[j * 19 + i] * z[i];
        o += sw2[j] * fmaxf(a, 0.f);
    }
    out[e] = o;
}

// ---------------- host ----------------
static void* sym_addr(const void* symbol) {
    void* p = nullptr;
    cudaGetSymbolAddress(&p, symbol);
    return p;
}

extern "C" void kernel_launch(void* const* d_in, const int* in_sizes, int n_in,
                              void* d_out, int out_size) {
    const float* x    = (const float*)d_in[0];
    const int*   ei   = (const int*)d_in[1];
    const float* ea   = (const float*)d_in[2];
    const float* yr   = (const float*)d_in[3];
    const float* qt   = (const float*)d_in[4];
    const float* W1   = (const float*)d_in[5];
    const float* a1s  = (const float*)d_in[6];
    const float* a1d  = (const float*)d_in[7];
    const float* b1   = (const float*)d_in[8];
    const float* W2   = (const float*)d_in[9];
    const float* a2s  = (const float*)d_in[10];
    const float* a2d  = (const float*)d_in[11];
    const float* b2   = (const float*)d_in[12];
    const float* W3   = (const float*)d_in[13];
    const float* a3s  = (const float*)d_in[14];
    const float* a3d  = (const float*)d_in[15];
    const float* b3   = (const float*)d_in[16];
    const float* f1w  = (const float*)d_in[17];
    const float* f1b  = (const float*)d_in[18];
    const float* f2w  = (const float*)d_in[19];
    const float* f2b  = (const float*)d_in[20];
    float* out = (float*)d_out;

    const int Nn = in_sizes[0] / 128;
    const int E  = in_sizes[1] / 2;

    float* h1 = (float*)sym_addr(g_h1);
    float* o1 = (float*)sym_addr(g_o1);
    float* h2 = (float*)sym_addr(g_h2);
    float* o2 = (float*)sym_addr(g_o2);
    float* h3 = (float*)sym_addr(g_h3);
    float* o3 = (float*)sym_addr(g_o3);
    float* sv = (float*)sym_addr(g_s);
    float* dv = (float*)sym_addr(g_d);
    float* al = (float*)sym_addr(g_alpha);
    int* counts = (int*)sym_addr(g_counts);
    int* rp     = (int*)sym_addr(g_rowptr);
    int* cur    = (int*)sym_addr(g_cursor);
    int* esrc   = (int*)sym_addr(g_esrc);
    int* epos   = (int*)sym_addr(g_epos);

    const int TB = 128;
    const int ET = E + Nn;

    // CSR (dst -> incoming src list), self-loops appended; epos = CSR slot per edge
    k_init_counts<<<(Nn + TB - 1) / TB, TB>>>(counts, Nn);
    k_count_edges<<<(E + TB - 1) / TB, TB>>>(ei, counts, E);
    k_scan<<<1, 1024>>>(counts, rp, cur, Nn);
    k_scatter<<<(ET + TB - 1) / TB, TB>>>(ei, cur, esrc, epos, E, Nn);

    // ---- layer 1: 128 -> 4x128 ----
    {
        dim3 g(512 / 128, (Nn + 127) / 128);
        mma_nt<<<g, 256>>>(x, W1, h1, Nn, 512, 128);
        k_sd_w<4, 128><<<(Nn * 4 * 32 + TB - 1) / TB, TB>>>(h1, a1s, a1d, sv, dv, Nn);
        k_alpha<4><<<(ET + TB - 1) / TB, TB>>>(sv, dv, ei, epos, al, E, Nn);
        gat_agg<4, 128, 32><<<(Nn * 32 + TB - 1) / TB, TB>>>(h1, al, b1, rp, esrc, o1, Nn);
    }
    // ---- layer 2: 512 -> 4x32 ----
    {
        dim3 g(128 / 128, (Nn + 127) / 128);
        mma_nt<<<g, 256>>>(o1, W2, h2, Nn, 128, 512);
        k_sd_w<4, 32><<<(Nn * 4 * 32 + TB - 1) / TB, TB>>>(h2, a2s, a2d, sv, dv, Nn);
        k_alpha<4><<<(ET + TB - 1) / TB, TB>>>(sv, dv, ei, epos, al, E, Nn);
        gat_agg<4, 32, 32><<<(Nn * 32 + TB - 1) / TB, TB>>>(h2, al, b2, rp, esrc, o2, Nn);
    }
    // ---- layer 3: 128 -> 1x8 ----
    {
        gemm_thin8<<<(Nn * 8 + 255) / 256, 256>>>(o2, W3, h3, Nn);
        k_sd_w<1, 8><<<(Nn * 32 + TB - 1) / TB, TB>>>(h3, a3s, a3d, sv, dv, Nn);
        k_alpha<1><<<(ET + TB - 1) / TB, TB>>>(sv, dv, ei, epos, al, E, Nn);
        gat_agg<1, 8, 8><<<(Nn * 8 + TB - 1) / TB, TB>>>(h3, al, b3, rp, esrc, o3, Nn);
    }
    // ---- edge MLP ----
    edge_mlp<<<(E + TB - 1) / TB, TB>>>(o3, ei, ea, yr, qt, f1w, f1b, f2w, f2b, out, E);
}

// round 8
// speedup vs baseline: 1.2264x; 1.2264x over previous
#include <cuda_runtime.h>
#include <math.h>

#define NMAX 50000
#define EMAX 400000

// ---------------- scratch (device globals; no dynamic allocation) ----------------
__device__ float g_h1[(size_t)NMAX * 512];   // layer1: aggregated-x (4 heads x 128)
__device__ float g_o1[(size_t)NMAX * 512];
__device__ float g_h2[(size_t)NMAX * 128];
__device__ float g_o2[(size_t)NMAX * 128];
__device__ float g_h3[NMAX * 8];
__device__ float g_o3[NMAX * 8];
__device__ float g_s[NMAX * 4];
__device__ float g_d[NMAX * 4];
__device__ float g_q[8 * 128];               // layer1 logit projection vectors
__device__ int   g_counts[NMAX];
__device__ int   g_rowptr[NMAX + 1];
__device__ int   g_cursor[NMAX];
__device__ int   g_esrc[EMAX + NMAX];

// ---------------- CSR construction ----------------
__global__ void k_init_counts(int* counts, int nn) {
    int i = blockIdx.x * blockDim.x + threadIdx.x;
    if (i < nn) counts[i] = 1;   // self-loop per node
}

__global__ void k_count_edges(const int* __restrict__ ei, int* counts, int E) {
    int i = blockIdx.x * blockDim.x + threadIdx.x;
    if (i < E) atomicAdd(&counts[ei[E + i]], 1);
}

__global__ void k_scan(const int* __restrict__ counts, int* rp, int* cur, int nn) {
    __shared__ int part[1024];
    int tid = threadIdx.x;
    int per = (nn + 1023) >> 10;
    int b = tid * per;
    int e = min(b + per, nn);
    int s = 0;
    for (int i = b; i < e; i++) s += counts[i];
    part[tid] = s;
    __syncthreads();
    if (tid == 0) {
        int run = 0;
        for (int i = 0; i < 1024; i++) { int v = part[i]; part[i] = run; run += v; }
    }
    __syncthreads();
    int run = part[tid];
    for (int i = b; i < e; i++) { rp[i] = run; cur[i] = run; run += counts[i]; }
    if (e == nn) rp[nn] = run;
}

__global__ void k_scatter(const int* __restrict__ ei, int* cur, int* esrc, int E, int nn) {
    int i = blockIdx.x * blockDim.x + threadIdx.x;
    if (i >= E + nn) return;
    int s, dd;
    if (i < E) { s = ei[i]; dd = ei[E + i]; }
    else       { s = i - E; dd = s; }
    int pos = atomicAdd(&cur[dd], 1);
    esrc[pos] = s;
}

// ---------------- layer-1 logit projections: q[hp][k] = sum_c a[h][c]*W1[h*128+c][k]
__global__ void k_proj(const float* __restrict__ W1, const float* __restrict__ a1s,
                       const float* __restrict__ a1d, float* __restrict__ q) {
    int hp = blockIdx.x;          // 0..7 (0-3: src proj, 4-7: dst proj)
    int h = hp & 3;
    const float* a = (hp < 4 ? a1s : a1d) + h * 128;
    __shared__ float sa[128];
    sa[threadIdx.x] = a[threadIdx.x];
    __syncthreads();
    int k = threadIdx.x;
    float sum = 0.f;
    for (int c = 0; c < 128; c++) sum += sa[c] * W1[(size_t)(h * 128 + c) * 128 + k];
    q[hp * 128 + k] = sum;
}

// ---------------- layer-1 s,d from x directly: warp per node -----------------------
__global__ void k_sd1(const float* __restrict__ x, const float* __restrict__ q,
                      float* __restrict__ s, float* __restrict__ d, int nn) {
    __shared__ float sq[8][128];
    for (int i = threadIdx.x; i < 1024; i += blockDim.x) sq[i >> 7][i & 127] = q[i];
    __syncthreads();
    int node = (blockIdx.x * blockDim.x + threadIdx.x) >> 5;
    int lane = threadIdx.x & 31;
    if (node >= nn) return;
    float4 v = *(const float4*)(x + (size_t)node * 128 + lane * 4);
    float sum[8];
#pragma unroll
    for (int j = 0; j < 8; j++) {
        const float* qp = &sq[j][lane * 4];
        sum[j] = v.x * qp[0] + v.y * qp[1] + v.z * qp[2] + v.w * qp[3];
    }
#pragma unroll
    for (int j = 0; j < 8; j++)
#pragma unroll
        for (int o = 16; o; o >>= 1) sum[j] += __shfl_xor_sync(0xffffffffu, sum[j], o);
    if (lane == 0) {
        *(float4*)(s + node * 4) = make_float4(sum[0], sum[1], sum[2], sum[3]);
        *(float4*)(d + node * 4) = make_float4(sum[4], sum[5], sum[6], sum[7]);
    }
}

// ---------------- layer-1 aggregation in x-space: warp per node --------------------
// aggx[n, h*128+k] = (sum_e w_eh * x[src_e, k]) / sum_e w_eh
__global__ void gat_agg_x(const float* __restrict__ x, const float* __restrict__ s,
                          const float* __restrict__ dvec,
                          const int* __restrict__ rp, const int* __restrict__ esrc,
                          float* __restrict__ aggx, int nn) {
    int node = (blockIdx.x * blockDim.x + threadIdx.x) >> 5;
    int lane = threadIdx.x & 31;
    if (node >= nn) return;
    float4 dv4 = *(const float4*)(dvec + node * 4);
    int beg = rp[node], end = rp[node + 1];
    float4 acc0 = make_float4(0.f, 0.f, 0.f, 0.f);
    float4 acc1 = acc0, acc2 = acc0, acc3 = acc0;
    float den0 = 0.f, den1 = 0.f, den2 = 0.f, den3 = 0.f;
#pragma unroll 2
    for (int i = beg; i < end; i++) {
        int sc = esrc[i];
        float4 sv = *(const float4*)(s + sc * 4);     // broadcast load
        float e0 = sv.x + dv4.x; e0 = e0 > 0.f ? e0 : 0.2f * e0;
        float e1 = sv.y + dv4.y; e1 = e1 > 0.f ? e1 : 0.2f * e1;
        float e2 = sv.z + dv4.z; e2 = e2 > 0.f ? e2 : 0.2f * e2;
        float e3 = sv.w + dv4.w; e3 = e3 > 0.f ? e3 : 0.2f * e3;
        float w0 = __expf(e0), w1 = __expf(e1), w2 = __expf(e2), w3 = __expf(e3);
        den0 += w0; den1 += w1; den2 += w2; den3 += w3;
        float4 v = *(const float4*)(x + (size_t)sc * 128 + lane * 4);
        acc0.x += w0 * v.x; acc0.y += w0 * v.y; acc0.z += w0 * v.z; acc0.w += w0 * v.w;
        acc1.x += w1 * v.x; acc1.y += w1 * v.y; acc1.z += w1 * v.z; acc1.w += w1 * v.w;
        acc2.x += w2 * v.x; acc2.y += w2 * v.y; acc2.z += w2 * v.z; acc2.w += w2 * v.w;
        acc3.x += w3 * v.x; acc3.y += w3 * v.y; acc3.z += w3 * v.z; acc3.w += w3 * v.w;
    }
    float i0 = 1.f / den0, i1 = 1.f / den1, i2 = 1.f / den2, i3 = 1.f / den3;
    float* op = aggx + (size_t)node * 512 + lane * 4;
    *(float4*)(op + 0)   = make_float4(acc0.x * i0, acc0.y * i0, acc0.z * i0, acc0.w * i0);
    *(float4*)(op + 128) = make_float4(acc1.x * i1, acc1.y * i1, acc1.z * i1, acc1.w * i1);
    *(float4*)(op + 256) = make_float4(acc2.x * i2, acc2.y * i2, acc2.z * i2, acc2.w * i2);
    *(float4*)(op + 384) = make_float4(acc3.x * i3, acc3.y * i3, acc3.z * i3, acc3.w * i3);
}

// ---------------- TF32 tensor-core GEMM: C = A @ B^T, grouped via blockIdx.z ------
// Optional per-column bias + elu epilogue. Requires N==128*gridDim.x, K%32==0.
__device__ __forceinline__ float f2tf32(float x) {
    unsigned u;
    asm("cvt.rna.tf32.f32 %0, %1;" : "=r"(u) : "f"(x));
    return __uint_as_float(u);
}

__global__ __launch_bounds__(256) void mma_nt(
    const float* __restrict__ A, const float* __restrict__ B,
    float* __restrict__ C, const float* __restrict__ bias,
    int M, int N, int K, int lda, int ldb, int ldc,
    int gA, int gB, int gC, int do_elu) {
    A += (size_t)blockIdx.z * gA;
    B += (size_t)blockIdx.z * gB;
    C += (size_t)blockIdx.z * gC;
    if (bias) bias += (size_t)blockIdx.z * N;
    __shared__ float As[128][36];
    __shared__ float Bs[128][36];
    const int t = threadIdx.x;
    const int lane = t & 31;
    const int wid = t >> 5;
    const int wm = (wid & 1) * 64;
    const int wn = (wid >> 1) * 32;
    const int group = lane >> 2, tig = lane & 3;
    const int bm = blockIdx.y * 128, bn = blockIdx.x * 128;
    const int lr = t >> 3;
    const int lc = (t & 7) * 4;

    float c[4][4][4];
#pragma unroll
    for (int i = 0; i < 4; i++)
#pragma unroll
        for (int j = 0; j < 4; j++)
#pragma unroll
            for (int q = 0; q < 4; q++) c[i][j][q] = 0.f;

    for (int kk = 0; kk < K; kk += 32) {
#pragma unroll
        for (int i = 0; i < 4; i++) {
            int m = lr + i * 32;
            int gm = bm + m;
            float4 av = make_float4(0.f, 0.f, 0.f, 0.f);
            if (gm < M) av = *(const float4*)(A + (size_t)gm * lda + kk + lc);
            As[m][lc + 0] = f2tf32(av.x); As[m][lc + 1] = f2tf32(av.y);
            As[m][lc + 2] = f2tf32(av.z); As[m][lc + 3] = f2tf32(av.w);
            float4 bv = make_float4(0.f, 0.f, 0.f, 0.f);
            if (bn + m < N) bv = *(const float4*)(B + (size_t)(bn + m) * ldb + kk + lc);
            Bs[m][lc + 0] = f2tf32(bv.x); Bs[m][lc + 1] = f2tf32(bv.y);
            Bs[m][lc + 2] = f2tf32(bv.z); Bs[m][lc + 3] = f2tf32(bv.w);
        }
        __syncthreads();
#pragma unroll
        for (int ks = 0; ks < 32; ks += 8) {
            unsigned bf[4][2];
#pragma unroll
            for (int nf = 0; nf < 4; nf++) {
                const float* bp = &Bs[wn + nf * 8 + group][ks + tig];
                bf[nf][0] = __float_as_uint(bp[0]);
                bf[nf][1] = __float_as_uint(bp[4]);
            }
#pragma unroll
            for (int mf = 0; mf < 4; mf++) {
                const float* ap0 = &As[wm + mf * 16 + group][ks + tig];
                const float* ap1 = &As[wm + mf * 16 + group + 8][ks + tig];
                unsigned a0 = __float_as_uint(ap0[0]);
                unsigned a1 = __float_as_uint(ap1[0]);
                unsigned a2 = __float_as_uint(ap0[4]);
                unsigned a3 = __float_as_uint(ap1[4]);
#pragma unroll
                for (int nf = 0; nf < 4; nf++) {
                    asm volatile(
                        "mma.sync.aligned.m16n8k8.row.col.f32.tf32.tf32.f32 "
                        "{%0,%1,%2,%3}, {%4,%5,%6,%7}, {%8,%9}, {%0,%1,%2,%3};"
                        : "+f"(c[mf][nf][0]), "+f"(c[mf][nf][1]),
                          "+f"(c[mf][nf][2]), "+f"(c[mf][nf][3])
                        : "r"(a0), "r"(a1), "r"(a2), "r"(a3),
                          "r"(bf[nf][0]), "r"(bf[nf][1]));
                }
            }
        }
        __syncthreads();
    }
#pragma unroll
    for (int mf = 0; mf < 4; mf++) {
        int m0 = bm + wm + mf * 16 + group;
        int m1 = m0 + 8;
#pragma unroll
        for (int nf = 0; nf < 4; nf++) {
            int n0 = bn + wn + nf * 8 + tig * 2;
            float v0 = c[mf][nf][0], v1 = c[mf][nf][1];
            float v2 = c[mf][nf][2], v3 = c[mf][nf][3];
            if (bias) {
                float b0 = bias[n0], b1v = bias[n0 + 1];
                v0 += b0; v1 += b1v; v2 += b0; v3 += b1v;
            }
            if (do_elu) {
                v0 = v0 > 0.f ? v0 : expm1f(v0);
                v1 = v1 > 0.f ? v1 : expm1f(v1);
                v2 = v2 > 0.f ? v2 : expm1f(v2);
                v3 = v3 > 0.f ? v3 : expm1f(v3);
            }
            if (m0 < M) *(float2*)(C + (size_t)m0 * ldc + n0) = make_float2(v0, v1);
            if (m1 < M) *(float2*)(C + (size_t)m1 * ldc + n0) = make_float2(v2, v3);
        }
    }
}

// ---------------- thin GEMM for layer 3: C[M,8] = A[M,128] @ W3[8,128]^T ----------
__global__ void gemm_thin8(const float* __restrict__ A, const float* __restrict__ B,
                           float* __restrict__ C, int M) {
    __shared__ float sB[8 * 128];
    for (int i = threadIdx.x; i < 8 * 128; i += blockDim.x) sB[i] = B[i];
    __syncthreads();
    int idx = blockIdx.x * blockDim.x + threadIdx.x;
    if (idx >= M * 8) return;
    int n = idx >> 3, j = idx & 7;
    const float* a = A + (size_t)n * 128;
    const float* w = sB + j * 128;
    float s = 0.f;
#pragma unroll
    for (int k = 0; k < 128; k += 4) {
        float4 v = *(const float4*)(a + k);
        s += v.x * w[k] + v.y * w[k + 1] + v.z * w[k + 2] + v.w * w[k + 3];
    }
    C[idx] = s;
}

// ---------------- per-node attention logits s,d: warp per (node,head) -------------
template <int H, int C>
__global__ void k_sd_w(const float* __restrict__ h, const float* __restrict__ as,
                       const float* __restrict__ ad, float* __restrict__ s,
                       float* __restrict__ d, int nn) {
    int w = (blockIdx.x * blockDim.x + threadIdx.x) >> 5;
    int lane = threadIdx.x & 31;
    if (w >= nn * H) return;
    int n = w / H, hh = w % H;
    float ss = 0.f, dd = 0.f;
    if (lane * 4 < C) {
        float4 v = *(const float4*)(h + (size_t)n * (H * C) + hh * C + lane * 4);
        float4 a = *(const float4*)(as + hh * C + lane * 4);
        float4 b = *(const float4*)(ad + hh * C + lane * 4);
        ss = v.x * a.x + v.y * a.y + v.z * a.z + v.w * a.w;
        dd = v.x * b.x + v.y * b.y + v.z * b.z + v.w * b.w;
    }
#pragma unroll
    for (int o = 16; o; o >>= 1) {
        ss += __shfl_xor_sync(0xffffffffu, ss, o);
        dd += __shfl_xor_sync(0xffffffffu, dd, o);
    }
    if (lane == 0) { s[w] = ss; d[w] = dd; }
}

// ---------------- GAT aggregation (atomic-free, CSR by dst, inline weights) -------
template <int H, int C, int LPN>
__global__ void gat_agg(const float* __restrict__ h, const float* __restrict__ s,
                        const float* __restrict__ dv, const float* __restrict__ bias,
                        const int* __restrict__ rp, const int* __restrict__ esrc,
                        float* __restrict__ out, int nn) {
    constexpr int F = H * C;
    constexpr int VPL = F / LPN;
    constexpr int NPW = 32 / LPN;
    int gwarp = (blockIdx.x * blockDim.x + threadIdx.x) >> 5;
    int lane = threadIdx.x & 31;
    int node = gwarp * NPW + lane / LPN;
    if (node >= nn) return;
    int sub = lane % LPN;
    int myh = (sub * VPL) / C;
    float dval = dv[node * H + myh];
    int beg = rp[node], end = rp[node + 1];

    float acc[VPL];
#pragma unroll
    for (int j = 0; j < VPL; j++) acc[j] = 0.f;
    float den = 0.f;
#pragma unroll 2
    for (int i = beg; i < end; i++) {
        int sc = esrc[i];
        float e = s[sc * H + myh] + dval;
        e = e > 0.f ? e : 0.2f * e;
        float w = __expf(e);
        den += w;
        if constexpr (VPL % 4 == 0) {
            const float4* hp4 = reinterpret_cast<const float4*>(h + (size_t)sc * F + sub * VPL);
#pragma unroll
            for (int j = 0; j < VPL / 4; j++) {
                float4 v = hp4[j];
                acc[4 * j + 0] += w * v.x;
                acc[4 * j + 1] += w * v.y;
                acc[4 * j + 2] += w * v.z;
                acc[4 * j + 3] += w * v.w;
            }
        } else {
            const float* hp = h + (size_t)sc * F + sub * VPL;
#pragma unroll
            for (int j = 0; j < VPL; j++) acc[j] += w * hp[j];
        }
    }
    float inv = 1.f / den;
#pragma unroll
    for (int j = 0; j < VPL; j++) {
        float v = acc[j] * inv + bias[sub * VPL + j];
        out[(size_t)node * F + sub * VPL + j] = v > 0.f ? v : expm1f(v);
    }
}

// ---------------- final edge MLP: 19 -> 16 -> 1 ----------------
__global__ void edge_mlp(const float* __restrict__ h3, const int* __restrict__ ei,
                         const float* __restrict__ ea, const float* __restrict__ yr,
                         const float* __restrict__ qt, const float* __restrict__ w1,
                         const float* __restrict__ b1, const float* __restrict__ w2,
                         const float* __restrict__ b2, float* __restrict__ out, int E) {
    __shared__ float sw1[16 * 19], sb1[16], sw2[16], sb2;
    for (int i = threadIdx.x; i < 16 * 19; i += blockDim.x) sw1[i] = w1[i];
    if (threadIdx.x < 16) { sb1[threadIdx.x] = b1[threadIdx.x]; sw2[threadIdx.x] = w2[threadIdx.x]; }
    if (threadIdx.x == 0) sb2 = b2[0];
    __syncthreads();
    int e = blockIdx.x * blockDim.x + threadIdx.x;
    if (e >= E) return;
    int si = ei[e], di = ei[E + e];
    float z[19];
#pragma unroll
    for (int j = 0; j < 8; j++) { z[j] = h3[si * 8 + j]; z[8 + j] = h3[di * 8 + j]; }
    z[16] = ea[e];
    z[17] = yr[e];
    z[18] = qt[e];
    float o = sb2;
#pragma unroll
    for (int j = 0; j < 16; j++) {
        float a = sb1[j];
#pragma unroll
        for (int i = 0; i < 19; i++) a += sw1[j * 19 + i] * z[i];
        o += sw2[j] * fmaxf(a, 0.f);
    }
    out[e] = o;
}

// ---------------- host ----------------
static void* sym_addr(const void* symbol) {
    void* p = nullptr;
    cudaGetSymbolAddress(&p, symbol);
    return p;
}

extern "C" void kernel_launch(void* const* d_in, const int* in_sizes, int n_in,
                              void* d_out, int out_size) {
    const float* x    = (const float*)d_in[0];
    const int*   ei   = (const int*)d_in[1];
    const float* ea   = (const float*)d_in[2];
    const float* yr   = (const float*)d_in[3];
    const float* qt   = (const float*)d_in[4];
    const float* W1   = (const float*)d_in[5];
    const float* a1s  = (const float*)d_in[6];
    const float* a1d  = (const float*)d_in[7];
    const float* b1   = (const float*)d_in[8];
    const float* W2   = (const float*)d_in[9];
    const float* a2s  = (const float*)d_in[10];
    const float* a2d  = (const float*)d_in[11];
    const float* b2   = (const float*)d_in[12];
    const float* W3   = (const float*)d_in[13];
    const float* a3s  = (const float*)d_in[14];
    const float* a3d  = (const float*)d_in[15];
    const float* b3   = (const float*)d_in[16];
    const float* f1w  = (const float*)d_in[17];
    const float* f1b  = (const float*)d_in[18];
    const float* f2w  = (const float*)d_in[19];
    const float* f2b  = (const float*)d_in[20];
    float* out = (float*)d_out;

    const int Nn = in_sizes[0] / 128;
    const int E  = in_sizes[1] / 2;

    float* aggx = (float*)sym_addr(g_h1);
    float* o1 = (float*)sym_addr(g_o1);
    float* h2 = (float*)sym_addr(g_h2);
    float* o2 = (float*)sym_addr(g_o2);
    float* h3 = (float*)sym_addr(g_h3);
    float* o3 = (float*)sym_addr(g_o3);
    float* sv = (float*)sym_addr(g_s);
    float* dv = (float*)sym_addr(g_d);
    float* q  = (float*)sym_addr(g_q);
    int* counts = (int*)sym_addr(g_counts);
    int* rp     = (int*)sym_addr(g_rowptr);
    int* cur    = (int*)sym_addr(g_cursor);
    int* esrc   = (int*)sym_addr(g_esrc);

    const int TB = 128;

    // CSR (dst -> incoming src list), self-loops appended
    k_init_counts<<<(Nn + TB - 1) / TB, TB>>>(counts, Nn);
    k_count_edges<<<(E + TB - 1) / TB, TB>>>(ei, counts, E);
    k_scan<<<1, 1024>>>(counts, rp, cur, Nn);
    k_scatter<<<(E + Nn + TB - 1) / TB, TB>>>(ei, cur, esrc, E, Nn);

    // ---- layer 1: aggregate x (128-dim), then grouped GEMM to 4x128 with elu ----
    {
        k_proj<<<8, 128>>>(W1, a1s, a1d, q);
        k_sd1<<<(Nn * 32 + 255) / 256, 256>>>(x, q, sv, dv, Nn);
        gat_agg_x<<<(Nn * 32 + TB - 1) / TB, TB>>>(x, sv, dv, rp, esrc, aggx, Nn);
        dim3 g(1, (Nn + 127) / 128, 4);
        mma_nt<<<g, 256>>>(aggx, W1, o1, b1, Nn, 128, 128,
                           512, 128, 512, 128, 128 * 128, 128, 1);
    }
    // ---- layer 2: 512 -> 4x32 ----
    {
        dim3 g(1, (Nn + 127) / 128, 1);
        mma_nt<<<g, 256>>>(o1, W2, h2, nullptr, Nn, 128, 512,
                           512, 512, 128, 0, 0, 0, 0);
        k_sd_w<4, 32><<<(Nn * 4 * 32 + TB - 1) / TB, TB>>>(h2, a2s, a2d, sv, dv, Nn);
        gat_agg<4, 32, 32><<<(Nn * 32 + TB - 1) / TB, TB>>>(h2, sv, dv, b2, rp, esrc, o2, Nn);
    }
    // ---- layer 3: 128 -> 1x8 ----
    {
        gemm_thin8<<<(Nn * 8 + 255) / 256, 256>>>(o2, W3, h3, Nn);
        k_sd_w<1, 8><<<(Nn * 32 + TB - 1) / TB, TB>>>(h3, a3s, a3d, sv, dv, Nn);
        gat_agg<1, 8, 8><<<(Nn * 8 + TB - 1) / TB, TB>>>(h3, sv, dv, b3, rp, esrc, o3, Nn);
    }
    // ---- edge MLP ----
    edge_mlp<<<(E + TB - 1) / TB, TB>>>(o3, ei, ea, yr, qt, f1w, f1b, f2w, f2b, out, E);
}

// round 9
// speedup vs baseline: 1.3339x; 1.0877x over previous
#include <cuda_runtime.h>
#include <math.h>

#define NMAX 50000
#define EMAX 400000

// ---------------- scratch (device globals; no dynamic allocation) ----------------
__device__ float g_h1[(size_t)NMAX * 512];   // layer1: aggregated-x (4 heads x 128)
__device__ float g_o1[(size_t)NMAX * 512];
__device__ float g_h2[(size_t)NMAX * 128];
__device__ float g_o2[(size_t)NMAX * 128];
__device__ float g_h3[NMAX * 8];
__device__ float g_o3[NMAX * 8];
__device__ float g_s[NMAX * 4];
__device__ float g_d[NMAX * 4];
__device__ float g_q[8 * 128];               // layer1 logit projection vectors
__device__ int   g_counts[NMAX];
__device__ int   g_rowptr[NMAX + 1];
__device__ int   g_cursor[NMAX];
__device__ int   g_esrc[EMAX + NMAX];

// ---------------- CSR construction ----------------
__global__ void k_init_counts(int* counts, int nn) {
    int i = blockIdx.x * blockDim.x + threadIdx.x;
    if (i < nn) counts[i] = 1;   // self-loop per node
}

__global__ void k_count_edges(const int* __restrict__ ei, int* counts, int E) {
    int i = blockIdx.x * blockDim.x + threadIdx.x;
    if (i < E) atomicAdd(&counts[ei[E + i]], 1);
}

__global__ void k_scan(const int* __restrict__ counts, int* rp, int* cur, int nn) {
    __shared__ int part[1024];
    int tid = threadIdx.x;
    int per = (nn + 1023) >> 10;
    int b = tid * per;
    int e = min(b + per, nn);
    int s = 0;
    for (int i = b; i < e; i++) s += counts[i];
    part[tid] = s;
    __syncthreads();
    if (tid == 0) {
        int run = 0;
        for (int i = 0; i < 1024; i++) { int v = part[i]; part[i] = run; run += v; }
    }
    __syncthreads();
    int run = part[tid];
    for (int i = b; i < e; i++) { rp[i] = run; cur[i] = run; run += counts[i]; }
    if (e == nn) rp[nn] = run;
}

__global__ void k_scatter(const int* __restrict__ ei, int* cur, int* esrc, int E, int nn) {
    int i = blockIdx.x * blockDim.x + threadIdx.x;
    if (i >= E + nn) return;
    int s, dd;
    if (i < E) { s = ei[i]; dd = ei[E + i]; }
    else       { s = i - E; dd = s; }
    int pos = atomicAdd(&cur[dd], 1);
    esrc[pos] = s;
}

// ---------------- layer-1 logit projections: q[hp][k] = sum_c a[h][c]*W1[h*128+c][k]
__global__ void k_proj(const float* __restrict__ W1, const float* __restrict__ a1s,
                       const float* __restrict__ a1d, float* __restrict__ q) {
    int hp = blockIdx.x;          // 0..7 (0-3: src proj, 4-7: dst proj)
    int h = hp & 3;
    const float* a = (hp < 4 ? a1s : a1d) + h * 128;
    __shared__ float sa[128];
    sa[threadIdx.x] = a[threadIdx.x];
    __syncthreads();
    int k = threadIdx.x;
    float sum = 0.f;
    for (int c = 0; c < 128; c++) sum += sa[c] * W1[(size_t)(h * 128 + c) * 128 + k];
    q[hp * 128 + k] = sum;
}

// ---------------- layer-1 s,d from x directly: warp per node -----------------------
__global__ void k_sd1(const float* __restrict__ x, const float* __restrict__ q,
                      float* __restrict__ s, float* __restrict__ d, int nn) {
    __shared__ float sq[8][128];
    for (int i = threadIdx.x; i < 1024; i += blockDim.x) sq[i >> 7][i & 127] = q[i];
    __syncthreads();
    int node = (blockIdx.x * blockDim.x + threadIdx.x) >> 5;
    int lane = threadIdx.x & 31;
    if (node >= nn) return;
    float4 v = *(const float4*)(x + (size_t)node * 128 + lane * 4);
    float sum[8];
#pragma unroll
    for (int j = 0; j < 8; j++) {
        const float* qp = &sq[j][lane * 4];
        sum[j] = v.x * qp[0] + v.y * qp[1] + v.z * qp[2] + v.w * qp[3];
    }
#pragma unroll
    for (int j = 0; j < 8; j++)
#pragma unroll
        for (int o = 16; o; o >>= 1) sum[j] += __shfl_xor_sync(0xffffffffu, sum[j], o);
    if (lane == 0) {
        *(float4*)(s + node * 4) = make_float4(sum[0], sum[1], sum[2], sum[3]);
        *(float4*)(d + node * 4) = make_float4(sum[4], sum[5], sum[6], sum[7]);
    }
}

// ---------------- layer-1 aggregation in x-space: warp per node --------------------
__global__ void gat_agg_x(const float* __restrict__ x, const float* __restrict__ s,
                          const float* __restrict__ dvec,
                          const int* __restrict__ rp, const int* __restrict__ esrc,
                          float* __restrict__ aggx, int nn) {
    int node = (blockIdx.x * blockDim.x + threadIdx.x) >> 5;
    int lane = threadIdx.x & 31;
    if (node >= nn) return;
    float4 dv4 = *(const float4*)(dvec + node * 4);
    int beg = rp[node], end = rp[node + 1];
    float4 acc0 = make_float4(0.f, 0.f, 0.f, 0.f);
    float4 acc1 = acc0, acc2 = acc0, acc3 = acc0;
    float den0 = 0.f, den1 = 0.f, den2 = 0.f, den3 = 0.f;
#pragma unroll 2
    for (int i = beg; i < end; i++) {
        int sc = esrc[i];
        float4 sv = *(const float4*)(s + sc * 4);     // broadcast load
        float e0 = sv.x + dv4.x; e0 = e0 > 0.f ? e0 : 0.2f * e0;
        float e1 = sv.y + dv4.y; e1 = e1 > 0.f ? e1 : 0.2f * e1;
        float e2 = sv.z + dv4.z; e2 = e2 > 0.f ? e2 : 0.2f * e2;
        float e3 = sv.w + dv4.w; e3 = e3 > 0.f ? e3 : 0.2f * e3;
        float w0 = __expf(e0), w1 = __expf(e1), w2 = __expf(e2), w3 = __expf(e3);
        den0 += w0; den1 += w1; den2 += w2; den3 += w3;
        float4 v = *(const float4*)(x + (size_t)sc * 128 + lane * 4);
        acc0.x += w0 * v.x; acc0.y += w0 * v.y; acc0.z += w0 * v.z; acc0.w += w0 * v.w;
        acc1.x += w1 * v.x; acc1.y += w1 * v.y; acc1.z += w1 * v.z; acc1.w += w1 * v.w;
        acc2.x += w2 * v.x; acc2.y += w2 * v.y; acc2.z += w2 * v.z; acc2.w += w2 * v.w;
        acc3.x += w3 * v.x; acc3.y += w3 * v.y; acc3.z += w3 * v.z; acc3.w += w3 * v.w;
    }
    float i0 = 1.f / den0, i1 = 1.f / den1, i2 = 1.f / den2, i3 = 1.f / den3;
    float* op = aggx + (size_t)node * 512 + lane * 4;
    *(float4*)(op + 0)   = make_float4(acc0.x * i0, acc0.y * i0, acc0.z * i0, acc0.w * i0);
    *(float4*)(op + 128) = make_float4(acc1.x * i1, acc1.y * i1, acc1.z * i1, acc1.w * i1);
    *(float4*)(op + 256) = make_float4(acc2.x * i2, acc2.y * i2, acc2.z * i2, acc2.w * i2);
    *(float4*)(op + 384) = make_float4(acc3.x * i3, acc3.y * i3, acc3.z * i3, acc3.w * i3);
}

// ---------------- TF32 tensor-core GEMM (double-buffered cp.async) ----------------
// C = A @ B^T, grouped via blockIdx.z. Raw f32 bits fed to tf32 mma (RZ truncation).
__device__ __forceinline__ void cpa16(void* dst, const void* src, int pred_bytes) {
    unsigned u = (unsigned)__cvta_generic_to_shared(dst);
    asm volatile("cp.async.cg.shared.global [%0], [%1], 16, %2;"
                 :: "r"(u), "l"(src), "r"(pred_bytes));
}

__global__ __launch_bounds__(256) void mma_nt(
    const float* __restrict__ A, const float* __restrict__ B,
    float* __restrict__ C, const float* __restrict__ bias,
    int M, int N, int K, int lda, int ldb, int ldc,
    int gA, int gB, int gC, int do_elu) {
    A += (size_t)blockIdx.z * gA;
    B += (size_t)blockIdx.z * gB;
    C += (size_t)blockIdx.z * gC;
    if (bias) bias += (size_t)blockIdx.z * N;
    __shared__ float As[2][128][36];
    __shared__ float Bs[2][128][36];
    const int t = threadIdx.x;
    const int lane = t & 31;
    const int wid = t >> 5;
    const int wm = (wid & 1) * 64;
    const int wn = (wid >> 1) * 32;
    const int group = lane >> 2, tig = lane & 3;
    const int bm = blockIdx.y * 128, bn = blockIdx.x * 128;
    const int lr = t >> 3;           // 0..31
    const int lc = (t & 7) * 4;      // 0,4,...,28

    float c[4][4][4];
#pragma unroll
    for (int i = 0; i < 4; i++)
#pragma unroll
        for (int j = 0; j < 4; j++)
#pragma unroll
            for (int q = 0; q < 4; q++) c[i][j][q] = 0.f;

    const int nsteps = K >> 5;

    auto load_stage = [&](int st, int kk) {
#pragma unroll
        for (int i = 0; i < 4; i++) {
            int m = lr + i * 32;
            int gm = bm + m;
            const float* asrc = A + (size_t)(gm < M ? gm : 0) * lda + kk + lc;
            cpa16(&As[st][m][lc], asrc, gm < M ? 16 : 0);
            int gn = bn + m;
            const float* bsrc = B + (size_t)(gn < N ? gn : 0) * ldb + kk + lc;
            cpa16(&Bs[st][m][lc], bsrc, gn < N ? 16 : 0);
        }
        asm volatile("cp.async.commit_group;");
    };

    load_stage(0, 0);

    for (int it = 0; it < nsteps; it++) {
        int st = it & 1;
        if (it + 1 < nsteps) {
            load_stage(st ^ 1, (it + 1) * 32);
            asm volatile("cp.async.wait_group 1;");
        } else {
            asm volatile("cp.async.wait_group 0;");
        }
        __syncthreads();
#pragma unroll
        for (int ks = 0; ks < 32; ks += 8) {
            unsigned bf[4][2];
#pragma unroll
            for (int nf = 0; nf < 4; nf++) {
                const float* bp = &Bs[st][wn + nf * 8 + group][ks + tig];
                bf[nf][0] = __float_as_uint(bp[0]);
                bf[nf][1] = __float_as_uint(bp[4]);
            }
#pragma unroll
            for (int mf = 0; mf < 4; mf++) {
                const float* ap0 = &As[st][wm + mf * 16 + group][ks + tig];
                const float* ap1 = &As[st][wm + mf * 16 + group + 8][ks + tig];
                unsigned a0 = __float_as_uint(ap0[0]);
                unsigned a1 = __float_as_uint(ap1[0]);
                unsigned a2 = __float_as_uint(ap0[4]);
                unsigned a3 = __float_as_uint(ap1[4]);
#pragma unroll
                for (int nf = 0; nf < 4; nf++) {
                    asm volatile(
                        "mma.sync.aligned.m16n8k8.row.col.f32.tf32.tf32.f32 "
                        "{%0,%1,%2,%3}, {%4,%5,%6,%7}, {%8,%9}, {%0,%1,%2,%3};"
                        : "+f"(c[mf][nf][0]), "+f"(c[mf][nf][1]),
                          "+f"(c[mf][nf][2]), "+f"(c[mf][nf][3])
                        : "r"(a0), "r"(a1), "r"(a2), "r"(a3),
                          "r"(bf[nf][0]), "r"(bf[nf][1]));
                }
            }
        }
        __syncthreads();
    }
#pragma unroll
    for (int mf = 0; mf < 4; mf++) {
        int m0 = bm + wm + mf * 16 + group;
        int m1 = m0 + 8;
#pragma unroll
        for (int nf = 0; nf < 4; nf++) {
            int n0 = bn + wn + nf * 8 + tig * 2;
            float v0 = c[mf][nf][0], v1 = c[mf][nf][1];
            float v2 = c[mf][nf][2], v3 = c[mf][nf][3];
            if (bias) {
                float b0 = bias[n0], b1v = bias[n0 + 1];
                v0 += b0; v1 += b1v; v2 += b0; v3 += b1v;
            }
            if (do_elu) {
                v0 = v0 > 0.f ? v0 : expm1f(v0);
                v1 = v1 > 0.f ? v1 : expm1f(v1);
                v2 = v2 > 0.f ? v2 : expm1f(v2);
                v3 = v3 > 0.f ? v3 : expm1f(v3);
            }
            if (m0 < M) *(float2*)(C + (size_t)m0 * ldc + n0) = make_float2(v0, v1);
            if (m1 < M) *(float2*)(C + (size_t)m1 * ldc + n0) = make_float2(v2, v3);
        }
    }
}

// ---------------- thin GEMM for layer 3: C[M,8] = A[M,128] @ W3[8,128]^T ----------
__global__ void gemm_thin8(const float* __restrict__ A, const float* __restrict__ B,
                           float* __restrict__ C, int M) {
    __shared__ float sB[8 * 128];
    for (int i = threadIdx.x; i < 8 * 128; i += blockDim.x) sB[i] = B[i];
    __syncthreads();
    int idx = blockIdx.x * blockDim.x + threadIdx.x;
    if (idx >= M * 8) return;
    int n = idx >> 3, j = idx & 7;
    const float* a = A + (size_t)n * 128;
    const float* w = sB + j * 128;
    float s = 0.f;
#pragma unroll
    for (int k = 0; k < 128; k += 4) {
        float4 v = *(const float4*)(a + k);
        s += v.x * w[k] + v.y * w[k + 1] + v.z * w[k + 2] + v.w * w[k + 3];
    }
    C[idx] = s;
}

// ---------------- per-node attention logits s,d: warp per (node,head) -------------
template <int H, int C>
__global__ void k_sd_w(const float* __restrict__ h, const float* __restrict__ as,
                       const float* __restrict__ ad, float* __restrict__ s,
                       float* __restrict__ d, int nn) {
    int w = (blockIdx.x * blockDim.x + threadIdx.x) >> 5;
    int lane = threadIdx.x & 31;
    if (w >= nn * H) return;
    int n = w / H, hh = w % H;
    float ss = 0.f, dd = 0.f;
    if (lane * 4 < C) {
        float4 v = *(const float4*)(h + (size_t)n * (H * C) + hh * C + lane * 4);
        float4 a = *(const float4*)(as + hh * C + lane * 4);
        float4 b = *(const float4*)(ad + hh * C + lane * 4);
        ss = v.x * a.x + v.y * a.y + v.z * a.z + v.w * a.w;
        dd = v.x * b.x + v.y * b.y + v.z * b.z + v.w * b.w;
    }
#pragma unroll
    for (int o = 16; o; o >>= 1) {
        ss += __shfl_xor_sync(0xffffffffu, ss, o);
        dd += __shfl_xor_sync(0xffffffffu, dd, o);
    }
    if (lane == 0) { s[w] = ss; d[w] = dd; }
}

// ---------------- GAT aggregation (atomic-free, CSR by dst, inline weights) -------
template <int H, int C, int LPN>
__global__ void gat_agg(const float* __restrict__ h, const float* __restrict__ s,
                        const float* __restrict__ dv, const float* __restrict__ bias,
                        const int* __restrict__ rp, const int* __restrict__ esrc,
                        float* __restrict__ out, int nn) {
    constexpr int F = H * C;
    constexpr int VPL = F / LPN;
    constexpr int NPW = 32 / LPN;
    int gwarp = (blockIdx.x * blockDim.x + threadIdx.x) >> 5;
    int lane = threadIdx.x & 31;
    int node = gwarp * NPW + lane / LPN;
    if (node >= nn) return;
    int sub = lane % LPN;
    int myh = (sub * VPL) / C;
    float dval = dv[node * H + myh];
    int beg = rp[node], end = rp[node + 1];

    float acc[VPL];
#pragma unroll
    for (int j = 0; j < VPL; j++) acc[j] = 0.f;
    float den = 0.f;
#pragma unroll 2
    for (int i = beg; i < end; i++) {
        int sc = esrc[i];
        float e = s[sc * H + myh] + dval;
        e = e > 0.f ? e : 0.2f * e;
        float w = __expf(e);
        den += w;
        if constexpr (VPL % 4 == 0) {
            const float4* hp4 = reinterpret_cast<const float4*>(h + (size_t)sc * F + sub * VPL);
#pragma unroll
            for (int j = 0; j < VPL / 4; j++) {
                float4 v = hp4[j];
                acc[4 * j + 0] += w * v.x;
                acc[4 * j + 1] += w * v.y;
                acc[4 * j + 2] += w * v.z;
                acc[4 * j + 3] += w * v.w;
            }
        } else {
            const float* hp = h + (size_t)sc * F + sub * VPL;
#pragma unroll
            for (int j = 0; j < VPL; j++) acc[j] += w * hp[j];
        }
    }
    float inv = 1.f / den;
#pragma unroll
    for (int j = 0; j < VPL; j++) {
        float v = acc[j] * inv + bias[sub * VPL + j];
        out[(size_t)node * F + sub * VPL + j] = v > 0.f ? v : expm1f(v);
    }
}

// ---------------- final edge MLP: 19 -> 16 -> 1 ----------------
__global__ void edge_mlp(const float* __restrict__ h3, const int* __restrict__ ei,
                         const float* __restrict__ ea, const float* __restrict__ yr,
                         const float* __restrict__ qt, const float* __restrict__ w1,
                         const float* __restrict__ b1, const float* __restrict__ w2,
                         const float* __restrict__ b2, float* __restrict__ out, int E) {
    __shared__ float sw1[16 * 19], sb1[16], sw2[16], sb2;
    for (int i = threadIdx.x; i < 16 * 19; i += blockDim.x) sw1[i] = w1[i];
    if (threadIdx.x < 16) { sb1[threadIdx.x] = b1[threadIdx.x]; sw2[threadIdx.x] = w2[threadIdx.x]; }
    if (threadIdx.x == 0) sb2 = b2[0];
    __syncthreads();
    int e = blockIdx.x * blockDim.x + threadIdx.x;
    if (e >= E) return;
    int si = ei[e], di = ei[E + e];
    float z[19];
#pragma unroll
    for (int j = 0; j < 8; j++) { z[j] = h3[si * 8 + j]; z[8 + j] = h3[di * 8 + j]; }
    z[16] = ea[e];
    z[17] = yr[e];
    z[18] = qt[e];
    float o = sb2;
#pragma unroll
    for (int j = 0; j < 16; j++) {
        float a = sb1[j];
#pragma unroll
        for (int i = 0; i < 19; i++) a += sw1[j * 19 + i] * z[i];
        o += sw2[j] * fmaxf(a, 0.f);
    }
    out[e] = o;
}

// ---------------- host ----------------
static void* sym_addr(const void* symbol) {
    void* p = nullptr;
    cudaGetSymbolAddress(&p, symbol);
    return p;
}

extern "C" void kernel_launch(void* const* d_in, const int* in_sizes, int n_in,
                              void* d_out, int out_size) {
    const float* x    = (const float*)d_in[0];
    const int*   ei   = (const int*)d_in[1];
    const float* ea   = (const float*)d_in[2];
    const float* yr   = (const float*)d_in[3];
    const float* qt   = (const float*)d_in[4];
    const float* W1   = (const float*)d_in[5];
    const float* a1s  = (const float*)d_in[6];
    const float* a1d  = (const float*)d_in[7];
    const float* b1   = (const float*)d_in[8];
    const float* W2   = (const float*)d_in[9];
    const float* a2s  = (const float*)d_in[10];
    const float* a2d  = (const float*)d_in[11];
    const float* b2   = (const float*)d_in[12];
    const float* W3   = (const float*)d_in[13];
    const float* a3s  = (const float*)d_in[14];
    const float* a3d  = (const float*)d_in[15];
    const float* b3   = (const float*)d_in[16];
    const float* f1w  = (const float*)d_in[17];
    const float* f1b  = (const float*)d_in[18];
    const float* f2w  = (const float*)d_in[19];
    const float* f2b  = (const float*)d_in[20];
    float* out = (float*)d_out;

    const int Nn = in_sizes[0] / 128;
    const int E  = in_sizes[1] / 2;

    float* aggx = (float*)sym_addr(g_h1);
    float* o1 = (float*)sym_addr(g_o1);
    float* h2 = (float*)sym_addr(g_h2);
    float* o2 = (float*)sym_addr(g_o2);
    float* h3 = (float*)sym_addr(g_h3);
    float* o3 = (float*)sym_addr(g_o3);
    float* sv = (float*)sym_addr(g_s);
    float* dv = (float*)sym_addr(g_d);
    float* q  = (float*)sym_addr(g_q);
    int* counts = (int*)sym_addr(g_counts);
    int* rp     = (int*)sym_addr(g_rowptr);
    int* cur    = (int*)sym_addr(g_cursor);
    int* esrc   = (int*)sym_addr(g_esrc);

    const int TB = 128;

    // CSR (dst -> incoming src list), self-loops appended
    k_init_counts<<<(Nn + TB - 1) / TB, TB>>>(counts, Nn);
    k_count_edges<<<(E + TB - 1) / TB, TB>>>(ei, counts, E);
    k_scan<<<1, 1024>>>(counts, rp, cur, Nn);
    k_scatter<<<(E + Nn + TB - 1) / TB, TB>>>(ei, cur, esrc, E, Nn);

    // ---- layer 1: aggregate x (128-dim), then grouped GEMM to 4x128 with elu ----
    {
        k_proj<<<8, 128>>>(W1, a1s, a1d, q);
        k_sd1<<<(Nn * 32 + 255) / 256, 256>>>(x, q, sv, dv, Nn);
        gat_agg_x<<<(Nn * 32 + TB - 1) / TB, TB>>>(x, sv, dv, rp, esrc, aggx, Nn);
        dim3 g(1, (Nn + 127) / 128, 4);
        mma_nt<<<g, 256>>>(aggx, W1, o1, b1, Nn, 128, 128,
                           512, 128, 512, 128, 128 * 128, 128, 1);
    }
    // ---- layer 2: 512 -> 4x32 ----
    {
        dim3 g(1, (Nn + 127) / 128, 1);
        mma_nt<<<g, 256>>>(o1, W2, h2, nullptr, Nn, 128, 512,
                           512, 512, 128, 0, 0, 0, 0);
        k_sd_w<4, 32><<<(Nn * 4 * 32 + TB - 1) / TB, TB>>>(h2, a2s, a2d, sv, dv, Nn);
        gat_agg<4, 32, 32><<<(Nn * 32 + TB - 1) / TB, TB>>>(h2, sv, dv, b2, rp, esrc, o2, Nn);
    }
    // ---- layer 3: 128 -> 1x8 ----
    {
        gemm_thin8<<<(Nn * 8 + 255) / 256, 256>>>(o2, W3, h3, Nn);
        k_sd_w<1, 8><<<(Nn * 32 + TB - 1) / TB, TB>>>(h3, a3s, a3d, sv, dv, Nn);
        gat_agg<1, 8, 8><<<(Nn * 8 + TB - 1) / TB, TB>>>(h3, sv, dv, b3, rp, esrc, o3, Nn);
    }
    // ---- edge MLP ----
    edge_mlp<<<(E + TB - 1) / TB, TB>>>(o3, ei, ea, yr, qt, f1w, f1b, f2w, f2b, out, E);
}

// round 11
// speedup vs baseline: 1.6309x; 1.2227x over previous
#include <cuda_runtime.h>
#include <math.h>

#define NMAX 50000
#define EMAX 400000

// ---------------- scratch (device globals; no dynamic allocation) ----------------
__device__ float g_h1[(size_t)NMAX * 512];   // layer1: aggregated-x (4 heads x 128)
__device__ float g_o1[(size_t)NMAX * 512];
__device__ float g_h2[(size_t)NMAX * 128];
__device__ float g_h3[NMAX * 8];
__device__ float g_o3[NMAX * 8];
__device__ float g_s[NMAX * 4];
__device__ float g_d[NMAX * 4];
__device__ float g_s3[NMAX];                 // layer-3 logits (separate: no aliasing!)
__device__ float g_d3[NMAX];
__device__ float g_q[8 * 128];               // layer1 logit projection vectors
__device__ int   g_counts[NMAX];
__device__ int   g_rowptr[NMAX + 1];
__device__ int   g_cursor[NMAX];
__device__ int   g_esrc[EMAX + NMAX];

// ---------------- CSR construction ----------------
__global__ void k_init_counts(int* counts, int nn) {
    int i = blockIdx.x * blockDim.x + threadIdx.x;
    if (i < nn) counts[i] = 1;   // self-loop per node
}

__global__ void k_count_edges(const int* __restrict__ ei, int* counts, int E) {
    int i = blockIdx.x * blockDim.x + threadIdx.x;
    if (i < E) atomicAdd(&counts[ei[E + i]], 1);
}

__global__ void k_scan(const int* __restrict__ counts, int* rp, int* cur, int nn) {
    __shared__ int part[1024];
    int tid = threadIdx.x;
    int per = (nn + 1023) >> 10;
    int b = tid * per;
    int e = min(b + per, nn);
    int s = 0;
    for (int i = b; i < e; i++) s += counts[i];
    part[tid] = s;
    __syncthreads();
    if (tid == 0) {
        int run = 0;
        for (int i = 0; i < 1024; i++) { int v = part[i]; part[i] = run; run += v; }
    }
    __syncthreads();
    int run = part[tid];
    for (int i = b; i < e; i++) { rp[i] = run; cur[i] = run; run += counts[i]; }
    if (e == nn) rp[nn] = run;
}

__global__ void k_scatter(const int* __restrict__ ei, int* cur, int* esrc, int E, int nn) {
    int i = blockIdx.x * blockDim.x + threadIdx.x;
    if (i >= E + nn) return;
    int s, dd;
    if (i < E) { s = ei[i]; dd = ei[E + i]; }
    else       { s = i - E; dd = s; }
    int pos = atomicAdd(&cur[dd], 1);
    esrc[pos] = s;
}

// ---------------- layer-1 logit projections: q[hp][k] = sum_c a[h][c]*W1[h*128+c][k]
__global__ void k_proj(const float* __restrict__ W1, const float* __restrict__ a1s,
                       const float* __restrict__ a1d, float* __restrict__ q) {
    int hp = blockIdx.x;          // 0..7 (0-3: src proj, 4-7: dst proj)
    int h = hp & 3;
    const float* a = (hp < 4 ? a1s : a1d) + h * 128;
    __shared__ float sa[128];
    sa[threadIdx.x] = a[threadIdx.x];
    __syncthreads();
    int k = threadIdx.x;
    float sum = 0.f;
    for (int c = 0; c < 128; c++) sum += sa[c] * W1[(size_t)(h * 128 + c) * 128 + k];
    q[hp * 128 + k] = sum;
}

// ---------------- layer-1 s,d from x directly: warp per node -----------------------
__global__ void k_sd1(const float* __restrict__ x, const float* __restrict__ q,
                      float* __restrict__ s, float* __restrict__ d, int nn) {
    __shared__ float sq[8][128];
    for (int i = threadIdx.x; i < 1024; i += blockDim.x) sq[i >> 7][i & 127] = q[i];
    __syncthreads();
    int node = (blockIdx.x * blockDim.x + threadIdx.x) >> 5;
    int lane = threadIdx.x & 31;
    if (node >= nn) return;
    float4 v = *(const float4*)(x + (size_t)node * 128 + lane * 4);
    float sum[8];
#pragma unroll
    for (int j = 0; j < 8; j++) {
        const float* qp = &sq[j][lane * 4];
        sum[j] = v.x * qp[0] + v.y * qp[1] + v.z * qp[2] + v.w * qp[3];
    }
#pragma unroll
    for (int j = 0; j < 8; j++)
#pragma unroll
        for (int o = 16; o; o >>= 1) sum[j] += __shfl_xor_sync(0xffffffffu, sum[j], o);
    if (lane == 0) {
        *(float4*)(s + node * 4) = make_float4(sum[0], sum[1], sum[2], sum[3]);
        *(float4*)(d + node * 4) = make_float4(sum[4], sum[5], sum[6], sum[7]);
    }
}

// ---------------- layer-1 aggregation in x-space: warp per node --------------------
__global__ void gat_agg_x(const float* __restrict__ x, const float* __restrict__ s,
                          const float* __restrict__ dvec,
                          const int* __restrict__ rp, const int* __restrict__ esrc,
                          float* __restrict__ aggx, int nn) {
    int node = (blockIdx.x * blockDim.x + threadIdx.x) >> 5;
    int lane = threadIdx.x & 31;
    if (node >= nn) return;
    float4 dv4 = *(const float4*)(dvec + node * 4);
    int beg = rp[node], end = rp[node + 1];
    float4 acc0 = make_float4(0.f, 0.f, 0.f, 0.f);
    float4 acc1 = acc0, acc2 = acc0, acc3 = acc0;
    float den0 = 0.f, den1 = 0.f, den2 = 0.f, den3 = 0.f;
#pragma unroll 2
    for (int i = beg; i < end; i++) {
        int sc = esrc[i];
        float4 sv = *(const float4*)(s + sc * 4);     // broadcast load
        float e0 = sv.x + dv4.x; e0 = e0 > 0.f ? e0 : 0.2f * e0;
        float e1 = sv.y + dv4.y; e1 = e1 > 0.f ? e1 : 0.2f * e1;
        float e2 = sv.z + dv4.z; e2 = e2 > 0.f ? e2 : 0.2f * e2;
        float e3 = sv.w + dv4.w; e3 = e3 > 0.f ? e3 : 0.2f * e3;
        float w0 = __expf(e0), w1 = __expf(e1), w2 = __expf(e2), w3 = __expf(e3);
        den0 += w0; den1 += w1; den2 += w2; den3 += w3;
        float4 v = *(const float4*)(x + (size_t)sc * 128 + lane * 4);
        acc0.x += w0 * v.x; acc0.y += w0 * v.y; acc0.z += w0 * v.z; acc0.w += w0 * v.w;
        acc1.x += w1 * v.x; acc1.y += w1 * v.y; acc1.z += w1 * v.z; acc1.w += w1 * v.w;
        acc2.x += w2 * v.x; acc2.y += w2 * v.y; acc2.z += w2 * v.z; acc2.w += w2 * v.w;
        acc3.x += w3 * v.x; acc3.y += w3 * v.y; acc3.z += w3 * v.z; acc3.w += w3 * v.w;
    }
    float i0 = 1.f / den0, i1 = 1.f / den1, i2 = 1.f / den2, i3 = 1.f / den3;
    float* op = aggx + (size_t)node * 512 + lane * 4;
    *(float4*)(op + 0)   = make_float4(acc0.x * i0, acc0.y * i0, acc0.z * i0, acc0.w * i0);
    *(float4*)(op + 128) = make_float4(acc1.x * i1, acc1.y * i1, acc1.z * i1, acc1.w * i1);
    *(float4*)(op + 256) = make_float4(acc2.x * i2, acc2.y * i2, acc2.z * i2, acc2.w * i2);
    *(float4*)(op + 384) = make_float4(acc3.x * i3, acc3.y * i3, acc3.z * i3, acc3.w * i3);
}

// ---------------- TF32 tensor-core GEMM (double-buffered cp.async) ----------------
// C = A @ B^T, grouped via blockIdx.z. Raw f32 bits fed to tf32 mma (RZ truncation).
// Optional fused epilogue: per-row s,d logits (sv!=null; requires N=128, bn=0,
// heads of 32 cols each, a_s/a_d = [4][32]).
__device__ __forceinline__ void cpa16(void* dst, const void* src, int pred_bytes) {
    unsigned u = (unsigned)__cvta_generic_to_shared(dst);
    asm volatile("cp.async.cg.shared.global [%0], [%1], 16, %2;"
                 :: "r"(u), "l"(src), "r"(pred_bytes));
}

__global__ __launch_bounds__(256) void mma_nt(
    const float* __restrict__ A, const float* __restrict__ B,
    float* __restrict__ C, const float* __restrict__ bias,
    const float* __restrict__ as_, const float* __restrict__ ad_,
    float* __restrict__ sv, float* __restrict__ dvv,
    int M, int N, int K, int lda, int ldb, int ldc,
    int gA, int gB, int gC, int do_elu) {
    A += (size_t)blockIdx.z * gA;
    B += (size_t)blockIdx.z * gB;
    C += (size_t)blockIdx.z * gC;
    if (bias) bias += (size_t)blockIdx.z * N;
    __shared__ float As[2][128][36];
    __shared__ float Bs[2][128][36];
    const int t = threadIdx.x;
    const int lane = t & 31;
    const int wid = t >> 5;
    const int wm = (wid & 1) * 64;
    const int wn = (wid >> 1) * 32;
    const int group = lane >> 2, tig = lane & 3;
    const int bm = blockIdx.y * 128, bn = blockIdx.x * 128;
    const int lr = t >> 3;           // 0..31
    const int lc = (t & 7) * 4;      // 0,4,...,28

    float c[4][4][4];
#pragma unroll
    for (int i = 0; i < 4; i++)
#pragma unroll
        for (int j = 0; j < 4; j++)
#pragma unroll
            for (int q = 0; q < 4; q++) c[i][j][q] = 0.f;

    const int nsteps = K >> 5;

    auto load_stage = [&](int st, int kk) {
#pragma unroll
        for (int i = 0; i < 4; i++) {
            int m = lr + i * 32;
            int gm = bm + m;
            const float* asrc = A + (size_t)(gm < M ? gm : 0) * lda + kk + lc;
            cpa16(&As[st][m][lc], asrc, gm < M ? 16 : 0);
            int gn = bn + m;
            const float* bsrc = B + (size_t)(gn < N ? gn : 0) * ldb + kk + lc;
            cpa16(&Bs[st][m][lc], bsrc, gn < N ? 16 : 0);
        }
        asm volatile("cp.async.commit_group;");
    };

    load_stage(0, 0);

    for (int it = 0; it < nsteps; it++) {
        int st = it & 1;
        if (it + 1 < nsteps) {
            load_stage(st ^ 1, (it + 1) * 32);
            asm volatile("cp.async.wait_group 1;");
        } else {
            asm volatile("cp.async.wait_group 0;");
        }
        __syncthreads();
#pragma unroll
        for (int ks = 0; ks < 32; ks += 8) {
            unsigned bf[4][2];
#pragma unroll
            for (int nf = 0; nf < 4; nf++) {
                const float* bp = &Bs[st][wn + nf * 8 + group][ks + tig];
                bf[nf][0] = __float_as_uint(bp[0]);
                bf[nf][1] = __float_as_uint(bp[4]);
            }
#pragma unroll
            for (int mf = 0; mf < 4; mf++) {
                const float* ap0 = &As[st][wm + mf * 16 + group][ks + tig];
                const float* ap1 = &As[st][wm + mf * 16 + group + 8][ks + tig];
                unsigned a0 = __float_as_uint(ap0[0]);
                unsigned a1 = __float_as_uint(ap1[0]);
                unsigned a2 = __float_as_uint(ap0[4]);
                unsigned a3 = __float_as_uint(ap1[4]);
#pragma unroll
                for (int nf = 0; nf < 4; nf++) {
                    asm volatile(
                        "mma.sync.aligned.m16n8k8.row.col.f32.tf32.tf32.f32 "
                        "{%0,%1,%2,%3}, {%4,%5,%6,%7}, {%8,%9}, {%0,%1,%2,%3};"
                        : "+f"(c[mf][nf][0]), "+f"(c[mf][nf][1]),
                          "+f"(c[mf][nf][2]), "+f"(c[mf][nf][3])
                        : "r"(a0), "r"(a1), "r"(a2), "r"(a3),
                          "r"(bf[nf][0]), "r"(bf[nf][1]));
                }
            }
        }
        __syncthreads();
    }
    const int head = wn >> 5;
#pragma unroll
    for (int mf = 0; mf < 4; mf++) {
        int m0 = bm + wm + mf * 16 + group;
        int m1 = m0 + 8;
        float ps0 = 0.f, pd0 = 0.f, ps1 = 0.f, pd1 = 0.f;
#pragma unroll
        for (int nf = 0; nf < 4; nf++) {
            int n0 = bn + wn + nf * 8 + tig * 2;
            float v0 = c[mf][nf][0], v1 = c[mf][nf][1];
            float v2 = c[mf][nf][2], v3 = c[mf][nf][3];
            if (bias) {
                float b0 = bias[n0], b1v = bias[n0 + 1];
                v0 += b0; v1 += b1v; v2 += b0; v3 += b1v;
            }
            if (do_elu) {
                v0 = v0 > 0.f ? v0 : expm1f(v0);
                v1 = v1 > 0.f ? v1 : expm1f(v1);
                v2 = v2 > 0.f ? v2 : expm1f(v2);
                v3 = v3 > 0.f ? v3 : expm1f(v3);
            }
            if (sv) {
                int cl = head * 32 + nf * 8 + tig * 2;
                float a0 = as_[cl], a1v = as_[cl + 1];
                float d0 = ad_[cl], d1v = ad_[cl + 1];
                ps0 += v0 * a0 + v1 * a1v;
                pd0 += v0 * d0 + v1 * d1v;
                ps1 += v2 * a0 + v3 * a1v;
                pd1 += v2 * d0 + v3 * d1v;
            }
            if (m0 < M) *(float2*)(C + (size_t)m0 * ldc + n0) = make_float2(v0, v1);
            if (m1 < M) *(float2*)(C + (size_t)m1 * ldc + n0) = make_float2(v2, v3);
        }
        if (sv) {
            // reduce over tig (lanes group*4 + {0..3})
            ps0 += __shfl_xor_sync(0xffffffffu, ps0, 1);
            ps0 += __shfl_xor_sync(0xffffffffu, ps0, 2);
            pd0 += __shfl_xor_sync(0xffffffffu, pd0, 1);
            pd0 += __shfl_xor_sync(0xffffffffu, pd0, 2);
            ps1 += __shfl_xor_sync(0xffffffffu, ps1, 1);
            ps1 += __shfl_xor_sync(0xffffffffu, ps1, 2);
            pd1 += __shfl_xor_sync(0xffffffffu, pd1, 1);
            pd1 += __shfl_xor_sync(0xffffffffu, pd1, 2);
            if (tig == 0) {
                if (m0 < M) { sv[m0 * 4 + head] = ps0; dvv[m0 * 4 + head] = pd0; }
                if (m1 < M) { sv[m1 * 4 + head] = ps1; dvv[m1 * 4 + head] = pd1; }
            }
        }
    }
}

// ---------------- layer-2 aggregation + fused layer-3 GEMM + logits ---------------
// Warp per node. Gathers h2 (4 heads x 32), bias+elu, then h3 = o2 @ W3^T (8 outs),
// s3,d3 = h3 . a3s/a3d. o2 is never materialized. s3/d3 are SEPARATE buffers.
__global__ void gat_agg2_f(const float* __restrict__ h, const float* __restrict__ s,
                           const float* __restrict__ dvec, const float* __restrict__ bias,
                           const int* __restrict__ rp, const int* __restrict__ esrc,
                           const float* __restrict__ W3, const float* __restrict__ a3s,
                           const float* __restrict__ a3d,
                           float* __restrict__ h3out, float* __restrict__ s3,
                           float* __restrict__ d3, int nn) {
    __shared__ float sW3[8 * 128];
    __shared__ float sa3[8], sd3c[8], sb2[128];
    for (int i = threadIdx.x; i < 1024; i += blockDim.x) sW3[i] = W3[i];
    if (threadIdx.x < 8) { sa3[threadIdx.x] = a3s[threadIdx.x]; sd3c[threadIdx.x] = a3d[threadIdx.x]; }
    for (int i = threadIdx.x; i < 128; i += blockDim.x) sb2[i] = bias[i];
    __syncthreads();

    int node = (blockIdx.x * blockDim.x + threadIdx.x) >> 5;
    int lane = threadIdx.x & 31;
    if (node >= nn) return;
    int myh = lane >> 3;                 // head for logits (8 lanes/head)
    float dval = dvec[node * 4 + myh];
    int beg = rp[node], end = rp[node + 1];

    float acc[4] = {0.f, 0.f, 0.f, 0.f};
    float den = 0.f;
#pragma unroll 2
    for (int i = beg; i < end; i++) {
        int sc = esrc[i];
        float e = s[sc * 4 + myh] + dval;
        e = e > 0.f ? e : 0.2f * e;
        float w = __expf(e);
        den += w;
        float4 v = *(const float4*)(h + (size_t)sc * 128 + lane * 4);
        acc[0] += w * v.x; acc[1] += w * v.y; acc[2] += w * v.z; acc[3] += w * v.w;
    }
    float inv = 1.f / den;
    float v[4];
#pragma unroll
    for (int j = 0; j < 4; j++) {
        float t = acc[j] * inv + sb2[lane * 4 + j];
        v[j] = t > 0.f ? t : expm1f(t);
    }
    // h3 partials: p[o] = sum_j v[j] * W3[o][lane*4+j]
    float p[8];
#pragma unroll
    for (int o = 0; o < 8; o++) {
        const float* w3 = &sW3[o * 128 + lane * 4];
        p[o] = v[0] * w3[0] + v[1] * w3[1] + v[2] * w3[2] + v[3] * w3[3];
    }
#pragma unroll
    for (int o = 0; o < 8; o++)
#pragma unroll
        for (int off = 16; off; off >>= 1) p[o] += __shfl_xor_sync(0xffffffffu, p[o], off);
    if (lane == 0) {
        float ss = 0.f, dd = 0.f;
#pragma unroll
        for (int o = 0; o < 8; o++) { ss += p[o] * sa3[o]; dd += p[o] * sd3c[o]; }
        *(float4*)(h3out + node * 8)     = make_float4(p[0], p[1], p[2], p[3]);
        *(float4*)(h3out + node * 8 + 4) = make_float4(p[4], p[5], p[6], p[7]);
        s3[node] = ss;
        d3[node] = dd;
    }
}

// ---------------- layer-3 aggregation (H=1, C=8, 8 lanes per node) -----------------
__global__ void gat_agg3(const float* __restrict__ h, const float* __restrict__ s,
                         const float* __restrict__ dv, const float* __restrict__ bias,
                         const int* __restrict__ rp, const int* __restrict__ esrc,
                         float* __restrict__ out, int nn) {
    int gwarp = (blockIdx.x * blockDim.x + threadIdx.x) >> 5;
    int lane = threadIdx.x & 31;
    int node = gwarp * 4 + lane / 8;
    if (node >= nn) return;
    int sub = lane & 7;
    float dval = dv[node];
    int beg = rp[node], end = rp[node + 1];
    float acc = 0.f, den = 0.f;
#pragma unroll 2
    for (int i = beg; i < end; i++) {
        int sc = esrc[i];
        float e = s[sc] + dval;
        e = e > 0.f ? e : 0.2f * e;
        float w = __expf(e);
        den += w;
        acc += w * h[sc * 8 + sub];
    }
    float vv = acc / den + bias[sub];
    out[node * 8 + sub] = vv > 0.f ? vv : expm1f(vv);
}

// ---------------- final edge MLP: 19 -> 16 -> 1 ----------------
__global__ void edge_mlp(const float* __restrict__ h3, const int* __restrict__ ei,
                         const float* __restrict__ ea, const float* __restrict__ yr,
                         const float* __restrict__ qt, const float* __restrict__ w1,
                         const float* __restrict__ b1, const float* __restrict__ w2,
                         const float* __restrict__ b2, float* __restrict__ out, int E) {
    __shared__ float sw1[16 * 19], sb1[16], sw2[16], sb2;
    for (int i = threadIdx.x; i < 16 * 19; i += blockDim.x) sw1[i] = w1[i];
    if (threadIdx.x < 16) { sb1[threadIdx.x] = b1[threadIdx.x]; sw2[threadIdx.x] = w2[threadIdx.x]; }
    if (threadIdx.x == 0) sb2 = b2[0];
    __syncthreads();
    int e = blockIdx.x * blockDim.x + threadIdx.x;
    if (e >= E) return;
    int si = ei[e], di = ei[E + e];
    float z[19];
#pragma unroll
    for (int j = 0; j < 8; j++) { z[j] = h3[si * 8 + j]; z[8 + j] = h3[di * 8 + j]; }
    z[16] = ea[e];
    z[17] = yr[e];
    z[18] = qt[e];
    float o = sb2;
#pragma unroll
    for (int j = 0; j < 16; j++) {
        float a = sb1[j];
#pragma unroll
        for (int i = 0; i < 19; i++) a += sw1[j * 19 + i] * z[i];
        o += sw2[j] * fmaxf(a, 0.f);
    }
    out[e] = o;
}

// ---------------- host ----------------
static void* sym_addr(const void* symbol) {
    void* p = nullptr;
    cudaGetSymbolAddress(&p, symbol);
    return p;
}

extern "C" void kernel_launch(void* const* d_in, const int* in_sizes, int n_in,
                              void* d_out, int out_size) {
    const float* x    = (const float*)d_in[0];
    const int*   ei   = (const int*)d_in[1];
    const float* ea   = (const float*)d_in[2];
    const float* yr   = (const float*)d_in[3];
    const float* qt   = (const float*)d_in[4];
    const float* W1   = (const float*)d_in[5];
    const float* a1s  = (const float*)d_in[6];
    const float* a1d  = (const float*)d_in[7];
    const float* b1   = (const float*)d_in[8];
    const float* W2   = (const float*)d_in[9];
    const float* a2s  = (const float*)d_in[10];
    const float* a2d  = (const float*)d_in[11];
    const float* b2   = (const float*)d_in[12];
    const float* W3   = (const float*)d_in[13];
    const float* a3s  = (const float*)d_in[14];
    const float* a3d  = (const float*)d_in[15];
    const float* b3   = (const float*)d_in[16];
    const float* f1w  = (const float*)d_in[17];
    const float* f1b  = (const float*)d_in[18];
    const float* f2w  = (const float*)d_in[19];
    const float* f2b  = (const float*)d_in[20];
    float* out = (float*)d_out;

    const int Nn = in_sizes[0] / 128;
    const int E  = in_sizes[1] / 2;

    float* aggx = (float*)sym_addr(g_h1);
    float* o1 = (float*)sym_addr(g_o1);
    float* h2 = (float*)sym_addr(g_h2);
    float* h3 = (float*)sym_addr(g_h3);
    float* o3 = (float*)sym_addr(g_o3);
    float* sv = (float*)sym_addr(g_s);
    float* dv = (float*)sym_addr(g_d);
    float* s3 = (float*)sym_addr(g_s3);
    float* d3 = (float*)sym_addr(g_d3);
    float* q  = (float*)sym_addr(g_q);
    int* counts = (int*)sym_addr(g_counts);
    int* rp     = (int*)sym_addr(g_rowptr);
    int* cur    = (int*)sym_addr(g_cursor);
    int* esrc   = (int*)sym_addr(g_esrc);

    const int TB = 128;

    // CSR (dst -> incoming src list), self-loops appended
    k_init_counts<<<(Nn + TB - 1) / TB, TB>>>(counts, Nn);
    k_count_edges<<<(E + TB - 1) / TB, TB>>>(ei, counts, E);
    k_scan<<<1, 1024>>>(counts, rp, cur, Nn);
    k_scatter<<<(E + Nn + TB - 1) / TB, TB>>>(ei, cur, esrc, E, Nn);

    // ---- layer 1: aggregate x (128-dim), then grouped GEMM to 4x128 with elu ----
    {
        k_proj<<<8, 128>>>(W1, a1s, a1d, q);
        k_sd1<<<(Nn * 32 + 255) / 256, 256>>>(x, q, sv, dv, Nn);
        gat_agg_x<<<(Nn * 32 + TB - 1) / TB, TB>>>(x, sv, dv, rp, esrc, aggx, Nn);
        dim3 g(1, (Nn + 127) / 128, 4);
        mma_nt<<<g, 256>>>(aggx, W1, o1, b1, nullptr, nullptr, nullptr, nullptr,
                           Nn, 128, 128, 512, 128, 512, 128, 128 * 128, 128, 1);
    }
    // ---- layer 2 GEMM (512 -> 128) with fused s,d logits ----
    {
        dim3 g(1, (Nn + 127) / 128, 1);
        mma_nt<<<g, 256>>>(o1, W2, h2, nullptr, a2s, a2d, sv, dv,
                           Nn, 128, 512, 512, 512, 128, 0, 0, 0, 0);
    }
    // ---- layer 2 aggregation + fused layer-3 GEMM + layer-3 logits (s3/d3!) ----
    gat_agg2_f<<<(Nn * 32 + TB - 1) / TB, TB>>>(h2, sv, dv, b2, rp, esrc,
                                                W3, a3s, a3d, h3, s3, d3, Nn);
    // ---- layer 3 aggregation ----
    gat_agg3<<<(Nn * 8 + TB - 1) / TB, TB>>>(h3, s3, d3, b3, rp, esrc, o3, Nn);
    // ---- edge MLP ----
    edge_mlp<<<(E + TB - 1) / TB, TB>>>(o3, ei, ea, yr, qt, f1w, f1b, f2w, f2b, out, E);
}

// round 13
// speedup vs baseline: 1.6399x; 1.0055x over previous
#include <cuda_runtime.h>
#include <math.h>

#define NMAX 50000
#define EMAX 400000

// ---------------- scratch (device globals; no dynamic allocation) ----------------
__device__ float g_h1[(size_t)NMAX * 512];   // layer1: aggregated-x (4 heads x 128)
__device__ float g_o1[(size_t)NMAX * 512];
__device__ float g_h2[(size_t)NMAX * 128];
__device__ float g_h3[NMAX * 8];
__device__ float g_o3[NMAX * 8];
__device__ float g_s[NMAX * 4];
__device__ float g_d[NMAX * 4];
__device__ float g_s3[NMAX];                 // layer-3 logits (separate: no aliasing)
__device__ float g_d3[NMAX];
__device__ float g_q[8 * 128];               // layer1 logit projection vectors
__device__ int   g_counts[NMAX];
__device__ int   g_rowptr[NMAX + 1];
__device__ int   g_cursor[NMAX];
__device__ int   g_esrc[EMAX + NMAX];

// ---------------- CSR construction ----------------
// counts[] is zeroed by cudaMemsetAsync; self-loop "+1" folded into the scan.
__global__ void k_count_edges(const int* __restrict__ ei, int* counts, int E) {
    int i = blockIdx.x * blockDim.x + threadIdx.x;
    if (i < E) atomicAdd(&counts[ei[E + i]], 1);
}

// Single-block scan with shfl-based block prefix (log-depth, no serial 1024-loop).
__global__ void k_scan(const int* __restrict__ counts, int* rp, int* cur, int nn) {
    __shared__ int wsum[32];
    int tid = threadIdx.x;
    int per = (nn + 1023) >> 10;
    int b = tid * per;
    int e = min(b + per, nn);
    int s = 0;
    for (int i = b; i < e; i++) s += counts[i] + 1;   // +1 = self-loop
    int lane = tid & 31, wid = tid >> 5;
    int v = s;
#pragma unroll
    for (int o = 1; o < 32; o <<= 1) {
        int t = __shfl_up_sync(0xffffffffu, v, o);
        if (lane >= o) v += t;
    }
    if (lane == 31) wsum[wid] = v;
    __syncthreads();
    if (wid == 0) {
        int w = wsum[lane];
#pragma unroll
        for (int o = 1; o < 32; o <<= 1) {
            int t = __shfl_up_sync(0xffffffffu, w, o);
            if (lane >= o) w += t;
        }
        wsum[lane] = w;
    }
    __syncthreads();
    int run = v - s + (wid > 0 ? wsum[wid - 1] : 0);   // exclusive prefix
    for (int i = b; i < e; i++) {
        rp[i] = run;
        cur[i] = run;
        run += counts[i] + 1;
    }
    if (e == nn) rp[nn] = run;
}

__global__ void k_scatter(const int* __restrict__ ei, int* cur, int* esrc, int E, int nn) {
    int i = blockIdx.x * blockDim.x + threadIdx.x;
    if (i >= E + nn) return;
    int s, dd;
    if (i < E) { s = ei[i]; dd = ei[E + i]; }
    else       { s = i - E; dd = s; }
    int pos = atomicAdd(&cur[dd], 1);
    esrc[pos] = s;
}

// ---------------- layer-1 logit projections ----------------
__global__ void k_proj(const float* __restrict__ W1, const float* __restrict__ a1s,
                       const float* __restrict__ a1d, float* __restrict__ q) {
    int hp = blockIdx.x;          // 0..7 (0-3: src proj, 4-7: dst proj)
    int h = hp & 3;
    const float* a = (hp < 4 ? a1s : a1d) + h * 128;
    __shared__ float sa[128];
    sa[threadIdx.x] = a[threadIdx.x];
    __syncthreads();
    int k = threadIdx.x;
    float sum = 0.f;
    for (int c = 0; c < 128; c++) sum += sa[c] * W1[(size_t)(h * 128 + c) * 128 + k];
    q[hp * 128 + k] = sum;
}

// ---------------- layer-1 s,d from x directly: warp per node ----------------
__global__ void k_sd1(const float* __restrict__ x, const float* __restrict__ q,
                      float* __restrict__ s, float* __restrict__ d, int nn) {
    __shared__ float sq[8][128];
    for (int i = threadIdx.x; i < 1024; i += blockDim.x) sq[i >> 7][i & 127] = q[i];
    __syncthreads();
    int node = (blockIdx.x * blockDim.x + threadIdx.x) >> 5;
    int lane = threadIdx.x & 31;
    if (node >= nn) return;
    float4 v = *(const float4*)(x + (size_t)node * 128 + lane * 4);
    float sum[8];
#pragma unroll
    for (int j = 0; j < 8; j++) {
        const float* qp = &sq[j][lane * 4];
        sum[j] = v.x * qp[0] + v.y * qp[1] + v.z * qp[2] + v.w * qp[3];
    }
#pragma unroll
    for (int j = 0; j < 8; j++)
#pragma unroll
        for (int o = 16; o; o >>= 1) sum[j] += __shfl_xor_sync(0xffffffffu, sum[j], o);
    if (lane == 0) {
        *(float4*)(s + node * 4) = make_float4(sum[0], sum[1], sum[2], sum[3]);
        *(float4*)(d + node * 4) = make_float4(sum[4], sum[5], sum[6], sum[7]);
    }
}

// ---------------- layer-1 aggregation in x-space: warp per node ----------------
__global__ void gat_agg_x(const float* __restrict__ x, const float* __restrict__ s,
                          const float* __restrict__ dvec,
                          const int* __restrict__ rp, const int* __restrict__ esrc,
                          float* __restrict__ aggx, int nn) {
    int node = (blockIdx.x * blockDim.x + threadIdx.x) >> 5;
    int lane = threadIdx.x & 31;
    if (node >= nn) return;
    float4 dv4 = *(const float4*)(dvec + node * 4);
    int beg = rp[node], end = rp[node + 1];
    float4 acc0 = make_float4(0.f, 0.f, 0.f, 0.f);
    float4 acc1 = acc0, acc2 = acc0, acc3 = acc0;
    float den0 = 0.f, den1 = 0.f, den2 = 0.f, den3 = 0.f;
#pragma unroll 2
    for (int i = beg; i < end; i++) {
        int sc = esrc[i];
        float4 sv = *(const float4*)(s + sc * 4);
        float e0 = sv.x + dv4.x; e0 = e0 > 0.f ? e0 : 0.2f * e0;
        float e1 = sv.y + dv4.y; e1 = e1 > 0.f ? e1 : 0.2f * e1;
        float e2 = sv.z + dv4.z; e2 = e2 > 0.f ? e2 : 0.2f * e2;
        float e3 = sv.w + dv4.w; e3 = e3 > 0.f ? e3 : 0.2f * e3;
        float w0 = __expf(e0), w1 = __expf(e1), w2 = __expf(e2), w3 = __expf(e3);
        den0 += w0; den1 += w1; den2 += w2; den3 += w3;
        float4 v = *(const float4*)(x + (size_t)sc * 128 + lane * 4);
        acc0.x += w0 * v.x; acc0.y += w0 * v.y; acc0.z += w0 * v.z; acc0.w += w0 * v.w;
        acc1.x += w1 * v.x; acc1.y += w1 * v.y; acc1.z += w1 * v.z; acc1.w += w1 * v.w;
        acc2.x += w2 * v.x; acc2.y += w2 * v.y; acc2.z += w2 * v.z; acc2.w += w2 * v.w;
        acc3.x += w3 * v.x; acc3.y += w3 * v.y; acc3.z += w3 * v.z; acc3.w += w3 * v.w;
    }
    float i0 = 1.f / den0, i1 = 1.f / den1, i2 = 1.f / den2, i3 = 1.f / den3;
    float* op = aggx + (size_t)node * 512 + lane * 4;
    *(float4*)(op + 0)   = make_float4(acc0.x * i0, acc0.y * i0, acc0.z * i0, acc0.w * i0);
    *(float4*)(op + 128) = make_float4(acc1.x * i1, acc1.y * i1, acc1.z * i1, acc1.w * i1);
    *(float4*)(op + 256) = make_float4(acc2.x * i2, acc2.y * i2, acc2.z * i2, acc2.w * i2);
    *(float4*)(op + 384) = make_float4(acc3.x * i3, acc3.y * i3, acc3.z * i3, acc3.w * i3);
}

// ---------------- TF32 tensor-core GEMM (double-buffered cp.async) ----------------
// C = A @ B^T, grouped via blockIdx.z. Raw f32 bits fed to tf32 mma (RZ truncation).
// Optional fused epilogue: per-row s,d logits (sv!=null; requires N=128, bn=0).
__device__ __forceinline__ void cpa16(void* dst, const void* src, int pred_bytes) {
    unsigned u = (unsigned)__cvta_generic_to_shared(dst);
    asm volatile("cp.async.cg.shared.global [%0], [%1], 16, %2;"
                 :: "r"(u), "l"(src), "r"(pred_bytes));
}

__global__ __launch_bounds__(256) void mma_nt(
    const float* __restrict__ A, const float* __restrict__ B,
    float* __restrict__ C, const float* __restrict__ bias,
    const float* __restrict__ as_, const float* __restrict__ ad_,
    float* __restrict__ sv, float* __restrict__ dvv,
    int M, int N, int K, int lda, int ldb, int ldc,
    int gA, int gB, int gC, int do_elu) {
    A += (size_t)blockIdx.z * gA;
    B += (size_t)blockIdx.z * gB;
    C += (size_t)blockIdx.z * gC;
    if (bias) bias += (size_t)blockIdx.z * N;
    __shared__ float As[2][128][36];
    __shared__ float Bs[2][128][36];
    const int t = threadIdx.x;
    const int lane = t & 31;
    const int wid = t >> 5;
    const int wm = (wid & 1) * 64;
    const int wn = (wid >> 1) * 32;
    const int group = lane >> 2, tig = lane & 3;
    const int bm = blockIdx.y * 128, bn = blockIdx.x * 128;
    const int lr = t >> 3;           // 0..31
    const int lc = (t & 7) * 4;      // 0,4,...,28

    float c[4][4][4];
#pragma unroll
    for (int i = 0; i < 4; i++)
#pragma unroll
        for (int j = 0; j < 4; j++)
#pragma unroll
            for (int q = 0; q < 4; q++) c[i][j][q] = 0.f;

    const int nsteps = K >> 5;

    auto load_stage = [&](int st, int kk) {
#pragma unroll
        for (int i = 0; i < 4; i++) {
            int m = lr + i * 32;
            int gm = bm + m;
            const float* asrc = A + (size_t)(gm < M ? gm : 0) * lda + kk + lc;
            cpa16(&As[st][m][lc], asrc, gm < M ? 16 : 0);
            int gn = bn + m;
            const float* bsrc = B + (size_t)(gn < N ? gn : 0) * ldb + kk + lc;
            cpa16(&Bs[st][m][lc], bsrc, gn < N ? 16 : 0);
        }
        asm volatile("cp.async.commit_group;");
    };

    load_stage(0, 0);

    for (int it = 0; it < nsteps; it++) {
        int st = it & 1;
        if (it + 1 < nsteps) {
            load_stage(st ^ 1, (it + 1) * 32);
            asm volatile("cp.async.wait_group 1;");
        } else {
            asm volatile("cp.async.wait_group 0;");
        }
        __syncthreads();
#pragma unroll
        for (int ks = 0; ks < 32; ks += 8) {
            unsigned bf[4][2];
#pragma unroll
            for (int nf = 0; nf < 4; nf++) {
                const float* bp = &Bs[st][wn + nf * 8 + group][ks + tig];
                bf[nf][0] = __float_as_uint(bp[0]);
                bf[nf][1] = __float_as_uint(bp[4]);
            }
#pragma unroll
            for (int mf = 0; mf < 4; mf++) {
                const float* ap0 = &As[st][wm + mf * 16 + group][ks + tig];
                const float* ap1 = &As[st][wm + mf * 16 + group + 8][ks + tig];
                unsigned a0 = __float_as_uint(ap0[0]);
                unsigned a1 = __float_as_uint(ap1[0]);
                unsigned a2 = __float_as_uint(ap0[4]);
                unsigned a3 = __float_as_uint(ap1[4]);
#pragma unroll
                for (int nf = 0; nf < 4; nf++) {
                    asm volatile(
                        "mma.sync.aligned.m16n8k8.row.col.f32.tf32.tf32.f32 "
                        "{%0,%1,%2,%3}, {%4,%5,%6,%7}, {%8,%9}, {%0,%1,%2,%3};"
                        : "+f"(c[mf][nf][0]), "+f"(c[mf][nf][1]),
                          "+f"(c[mf][nf][2]), "+f"(c[mf][nf][3])
                        : "r"(a0), "r"(a1), "r"(a2), "r"(a3),
                          "r"(bf[nf][0]), "r"(bf[nf][1]));
                }
            }
        }
        __syncthreads();
    }
    const int head = wn >> 5;
#pragma unroll
    for (int mf = 0; mf < 4; mf++) {
        int m0 = bm + wm + mf * 16 + group;
        int m1 = m0 + 8;
        float ps0 = 0.f, pd0 = 0.f, ps1 = 0.f, pd1 = 0.f;
#pragma unroll
        for (int nf = 0; nf < 4; nf++) {
            int n0 = bn + wn + nf * 8 + tig * 2;
            float v0 = c[mf][nf][0], v1 = c[mf][nf][1];
            float v2 = c[mf][nf][2], v3 = c[mf][nf][3];
            if (bias) {
                float b0 = bias[n0], b1v = bias[n0 + 1];
                v0 += b0; v1 += b1v; v2 += b0; v3 += b1v;
            }
            if (do_elu) {
                v0 = v0 > 0.f ? v0 : expm1f(v0);
                v1 = v1 > 0.f ? v1 : expm1f(v1);
                v2 = v2 > 0.f ? v2 : expm1f(v2);
                v3 = v3 > 0.f ? v3 : expm1f(v3);
            }
            if (sv) {
                int cl = head * 32 + nf * 8 + tig * 2;
                float a0 = as_[cl], a1v = as_[cl + 1];
                float d0 = ad_[cl], d1v = ad_[cl + 1];
                ps0 += v0 * a0 + v1 * a1v;
                pd0 += v0 * d0 + v1 * d1v;
                ps1 += v2 * a0 + v3 * a1v;
                pd1 += v2 * d0 + v3 * d1v;
            }
            if (m0 < M) *(float2*)(C + (size_t)m0 * ldc + n0) = make_float2(v0, v1);
            if (m1 < M) *(float2*)(C + (size_t)m1 * ldc + n0) = make_float2(v2, v3);
        }
        if (sv) {
            ps0 += __shfl_xor_sync(0xffffffffu, ps0, 1);
            ps0 += __shfl_xor_sync(0xffffffffu, ps0, 2);
            pd0 += __shfl_xor_sync(0xffffffffu, pd0, 1);
            pd0 += __shfl_xor_sync(0xffffffffu, pd0, 2);
            ps1 += __shfl_xor_sync(0xffffffffu, ps1, 1);
            ps1 += __shfl_xor_sync(0xffffffffu, ps1, 2);
            pd1 += __shfl_xor_sync(0xffffffffu, pd1, 1);
            pd1 += __shfl_xor_sync(0xffffffffu, pd1, 2);
            if (tig == 0) {
                if (m0 < M) { sv[m0 * 4 + head] = ps0; dvv[m0 * 4 + head] = pd0; }
                if (m1 < M) { sv[m1 * 4 + head] = ps1; dvv[m1 * 4 + head] = pd1; }
            }
        }
    }
}

// ---------------- layer-2 aggregation + fused layer-3 GEMM + logits ---------------
__global__ void gat_agg2_f(const float* __restrict__ h, const float* __restrict__ s,
                           const float* __restrict__ dvec, const float* __restrict__ bias,
                           const int* __restrict__ rp, const int* __restrict__ esrc,
                           const float* __restrict__ W3, const float* __restrict__ a3s,
                           const float* __restrict__ a3d,
                           float* __restrict__ h3out, float* __restrict__ s3,
                           float* __restrict__ d3, int nn) {
    __shared__ float sW3[8 * 128];
    __shared__ float sa3[8], sd3c[8], sb2[128];
    for (int i = threadIdx.x; i < 1024; i += blockDim.x) sW3[i] = W3[i];
    if (threadIdx.x < 8) { sa3[threadIdx.x] = a3s[threadIdx.x]; sd3c[threadIdx.x] = a3d[threadIdx.x]; }
    for (int i = threadIdx.x; i < 128; i += blockDim.x) sb2[i] = bias[i];
    __syncthreads();

    int node = (blockIdx.x * blockDim.x + threadIdx.x) >> 5;
    int lane = threadIdx.x & 31;
    if (node >= nn) return;
    int myh = lane >> 3;
    float dval = dvec[node * 4 + myh];
    int beg = rp[node], end = rp[node + 1];

    float acc[4] = {0.f, 0.f, 0.f, 0.f};
    float den = 0.f;
#pragma unroll 2
    for (int i = beg; i < end; i++) {
        int sc = esrc[i];
        float e = s[sc * 4 + myh] + dval;
        e = e > 0.f ? e : 0.2f * e;
        float w = __expf(e);
        den += w;
        float4 v = *(const float4*)(h + (size_t)sc * 128 + lane * 4);
        acc[0] += w * v.x; acc[1] += w * v.y; acc[2] += w * v.z; acc[3] += w * v.w;
    }
    float inv = 1.f / den;
    float v[4];
#pragma unroll
    for (int j = 0; j < 4; j++) {
        float t = acc[j] * inv + sb2[lane * 4 + j];
        v[j] = t > 0.f ? t : expm1f(t);
    }
    float p[8];
#pragma unroll
    for (int o = 0; o < 8; o++) {
        const float* w3 = &sW3[o * 128 + lane * 4];
        p[o] = v[0] * w3[0] + v[1] * w3[1] + v[2] * w3[2] + v[3] * w3[3];
    }
#pragma unroll
    for (int o = 0; o < 8; o++)
#pragma unroll
        for (int off = 16; off; off >>= 1) p[o] += __shfl_xor_sync(0xffffffffu, p[o], off);
    if (lane == 0) {
        float ss = 0.f, dd = 0.f;
#pragma unroll
        for (int o = 0; o < 8; o++) { ss += p[o] * sa3[o]; dd += p[o] * sd3c[o]; }
        *(float4*)(h3out + node * 8)     = make_float4(p[0], p[1], p[2], p[3]);
        *(float4*)(h3out + node * 8 + 4) = make_float4(p[4], p[5], p[6], p[7]);
        s3[node] = ss;
        d3[node] = dd;
    }
}

// ---------------- layer-3 aggregation ----------------
__global__ void gat_agg3(const float* __restrict__ h, const float* __restrict__ s,
                         const float* __restrict__ dv, const float* __restrict__ bias,
                         const int* __restrict__ rp, const int* __restrict__ esrc,
                         float* __restrict__ out, int nn) {
    int gwarp = (blockIdx.x * blockDim.x + threadIdx.x) >> 5;
    int lane = threadIdx.x & 31;
    int node = gwarp * 4 + lane / 8;
    if (node >= nn) return;
    int sub = lane & 7;
    float dval = dv[node];
    int beg = rp[node], end = rp[node + 1];
    float acc = 0.f, den = 0.f;
#pragma unroll 2
    for (int i = beg; i < end; i++) {
        int sc = esrc[i];
        float e = s[sc] + dval;
        e = e > 0.f ? e : 0.2f * e;
        float w = __expf(e);
        den += w;
        acc += w * h[sc * 8 + sub];
    }
    float vv = acc / den + bias[sub];
    out[node * 8 + sub] = vv > 0.f ? vv : expm1f(vv);
}

// ---------------- final edge MLP: 19 -> 16 -> 1 ----------------
__global__ void edge_mlp(const float* __restrict__ h3, const int* __restrict__ ei,
                         const float* __restrict__ ea, const float* __restrict__ yr,
                         const float* __restrict__ qt, const float* __restrict__ w1,
                         const float* __restrict__ b1, const float* __restrict__ w2,
                         const float* __restrict__ b2, float* __restrict__ out, int E) {
    __shared__ float sw1[16 * 19], sb1[16], sw2[16], sb2;
    for (int i = threadIdx.x; i < 16 * 19; i += blockDim.x) sw1[i] = w1[i];
    if (threadIdx.x < 16) { sb1[threadIdx.x] = b1[threadIdx.x]; sw2[threadIdx.x] = w2[threadIdx.x]; }
    if (threadIdx.x == 0) sb2 = b2[0];
    __syncthreads();
    int e = blockIdx.x * blockDim.x + threadIdx.x;
    if (e >= E) return;
    int si = ei[e], di = ei[E + e];
    float z[19];
#pragma unroll
    for (int j = 0; j < 8; j++) { z[j] = h3[si * 8 + j]; z[8 + j] = h3[di * 8 + j]; }
    z[16] = ea[e];
    z[17] = yr[e];
    z[18] = qt[e];
    float o = sb2;
#pragma unroll
    for (int j = 0; j < 16; j++) {
        float a = sb1[j];
#pragma unroll
        for (int i = 0; i < 19; i++) a += sw1[j * 19 + i] * z[i];
        o += sw2[j] * fmaxf(a, 0.f);
    }
    out[e] = o;
}

// ---------------- host ----------------
static void* sym_addr(const void* symbol) {
    void* p = nullptr;
    cudaGetSymbolAddress(&p, symbol);
    return p;
}

extern "C" void kernel_launch(void* const* d_in, const int* in_sizes, int n_in,
                              void* d_out, int out_size) {
    const float* x    = (const float*)d_in[0];
    const int*   ei   = (const int*)d_in[1];
    const float* ea   = (const float*)d_in[2];
    const float* yr   = (const float*)d_in[3];
    const float* qt   = (const float*)d_in[4];
    const float* W1   = (const float*)d_in[5];
    const float* a1s  = (const float*)d_in[6];
    const float* a1d  = (const float*)d_in[7];
    const float* b1   = (const float*)d_in[8];
    const float* W2   = (const float*)d_in[9];
    const float* a2s  = (const float*)d_in[10];
    const float* a2d  = (const float*)d_in[11];
    const float* b2   = (const float*)d_in[12];
    const float* W3   = (const float*)d_in[13];
    const float* a3s  = (const float*)d_in[14];
    const float* a3d  = (const float*)d_in[15];
    const float* b3   = (const float*)d_in[16];
    const float* f1w  = (const float*)d_in[17];
    const float* f1b  = (const float*)d_in[18];
    const float* f2w  = (const float*)d_in[19];
    const float* f2b  = (const float*)d_in[20];
    float* out = (float*)d_out;

    const int Nn = in_sizes[0] / 128;
    const int E  = in_sizes[1] / 2;

    float* aggx = (float*)sym_addr(g_h1);
    float* o1 = (float*)sym_addr(g_o1);
    float* h2 = (float*)sym_addr(g_h2);
    float* h3 = (float*)sym_addr(g_h3);
    float* o3 = (float*)sym_addr(g_o3);
    float* sv = (float*)sym_addr(g_s);
    float* dv = (float*)sym_addr(g_d);
    float* s3 = (float*)sym_addr(g_s3);
    float* d3 = (float*)sym_addr(g_d3);
    float* q  = (float*)sym_addr(g_q);
    int* counts = (int*)sym_addr(g_counts);
    int* rp     = (int*)sym_addr(g_rowptr);
    int* cur    = (int*)sym_addr(g_cursor);
    int* esrc   = (int*)sym_addr(g_esrc);

    const int TB = 128;

    // CSR (dst -> incoming src list); self-loop "+1" folded into the scan.
    cudaMemsetAsync(counts, 0, Nn * sizeof(int));
    k_count_edges<<<(E + TB - 1) / TB, TB>>>(ei, counts, E);
    k_scan<<<1, 1024>>>(counts, rp, cur, Nn);
    k_scatter<<<(E + Nn + TB - 1) / TB, TB>>>(ei, cur, esrc, E, Nn);

    // ---- layer 1: aggregate x (128-dim), then grouped GEMM to 4x128 with elu ----
    {
        k_proj<<<8, 128>>>(W1, a1s, a1d, q);
        k_sd1<<<(Nn * 32 + 255) / 256, 256>>>(x, q, sv, dv, Nn);
        gat_agg_x<<<(Nn * 32 + TB - 1) / TB, TB>>>(x, sv, dv, rp, esrc, aggx, Nn);
        dim3 g(1, (Nn + 127) / 128, 4);
        mma_nt<<<g, 256>>>(aggx, W1, o1, b1, nullptr, nullptr, nullptr, nullptr,
                           Nn, 128, 128, 512, 128, 512, 128, 128 * 128, 128, 1);
    }
    // ---- layer 2 GEMM (512 -> 128) with fused s,d logits ----
    {
        dim3 g(1, (Nn + 127) / 128, 1);
        mma_nt<<<g, 256>>>(o1, W2, h2, nullptr, a2s, a2d, sv, dv,
                           Nn, 128, 512, 512, 512, 128, 0, 0, 0, 0);
    }
    // ---- layer 2 aggregation + fused layer-3 GEMM + layer-3 logits ----
    gat_agg2_f<<<(Nn * 32 + TB - 1) / TB, TB>>>(h2, sv, dv, b2, rp, esrc,
                                                W3, a3s, a3d, h3, s3, d3, Nn);
    // ---- layer 3 aggregation ----
    gat_agg3<<<(Nn * 8 + TB - 1) / TB, TB>>>(h3, s3, d3, b3, rp, esrc, o3, Nn);
    // ---- edge MLP ----
    edge_mlp<<<(E + TB - 1) / TB, TB>>>(o3, ei, ea, yr, qt, f1w, f1b, f2w, f2b, out, E);
}

// round 14
// speedup vs baseline: 1.8162x; 1.1075x over previous
#include <cuda_runtime.h>
#include <math.h>

#define NMAX 50000
#define EMAX 400000

// ---------------- scratch (device globals; no dynamic allocation) ----------------
__device__ float g_h1[(size_t)NMAX * 512];   // layer1: aggregated-x (4 heads x 128)
__device__ float g_o1[(size_t)NMAX * 512];
__device__ float g_h2[(size_t)NMAX * 128];
__device__ float g_h3[NMAX * 8];
__device__ float g_o3[NMAX * 8];
__device__ float g_s[NMAX * 4];
__device__ float g_d[NMAX * 4];
__device__ float g_s3[NMAX];                 // layer-3 logits (separate: no aliasing)
__device__ float g_d3[NMAX];
__device__ float g_q[8 * 128];               // layer1 logit projection vectors
__device__ int   g_counts[NMAX];
__device__ int   g_rowptr[NMAX + 1];
__device__ int   g_cursor[NMAX];
__device__ int   g_esrc[EMAX + NMAX];

// ---------------- CSR construction ----------------
// counts[] is zeroed by cudaMemsetAsync; self-loop "+1" folded into the scan.
__global__ void k_count_edges(const int* __restrict__ ei, int* counts, int E) {
    int i = blockIdx.x * blockDim.x + threadIdx.x;
    if (i < E) atomicAdd(&counts[ei[E + i]], 1);
}

// Single-block scan with shfl-based block prefix (log-depth).
__global__ void k_scan(const int* __restrict__ counts, int* rp, int* cur, int nn) {
    __shared__ int wsum[32];
    int tid = threadIdx.x;
    int per = (nn + 1023) >> 10;
    int b = tid * per;
    int e = min(b + per, nn);
    int s = 0;
    for (int i = b; i < e; i++) s += counts[i] + 1;   // +1 = self-loop
    int lane = tid & 31, wid = tid >> 5;
    int v = s;
#pragma unroll
    for (int o = 1; o < 32; o <<= 1) {
        int t = __shfl_up_sync(0xffffffffu, v, o);
        if (lane >= o) v += t;
    }
    if (lane == 31) wsum[wid] = v;
    __syncthreads();
    if (wid == 0) {
        int w = wsum[lane];
#pragma unroll
        for (int o = 1; o < 32; o <<= 1) {
            int t = __shfl_up_sync(0xffffffffu, w, o);
            if (lane >= o) w += t;
        }
        wsum[lane] = w;
    }
    __syncthreads();
    int run = v - s + (wid > 0 ? wsum[wid - 1] : 0);   // exclusive prefix
    for (int i = b; i < e; i++) {
        rp[i] = run;
        cur[i] = run;
        run += counts[i] + 1;
    }
    if (e == nn) rp[nn] = run;
}

__global__ void k_scatter(const int* __restrict__ ei, int* cur, int* esrc, int E, int nn) {
    int i = blockIdx.x * blockDim.x + threadIdx.x;
    if (i >= E + nn) return;
    int s, dd;
    if (i < E) { s = ei[i]; dd = ei[E + i]; }
    else       { s = i - E; dd = s; }
    int pos = atomicAdd(&cur[dd], 1);
    esrc[pos] = s;
}

// ---------------- layer-1 logit projections (parallel reduction) ------------------
// q[hp][k] = sum_c a[h][c] * W1[(h*128+c)*128 + k]; 8 c-chunks of 16 per block.
__global__ __launch_bounds__(1024) void k_proj(
    const float* __restrict__ W1, const float* __restrict__ a1s,
    const float* __restrict__ a1d, float* __restrict__ q) {
    int hp = blockIdx.x;          // 0..7 (0-3: src proj, 4-7: dst proj)
    int h = hp & 3;
    const float* a = (hp < 4 ? a1s : a1d) + h * 128;
    __shared__ float sa[128];
    __shared__ float part[8][128];
    if (threadIdx.x < 128) sa[threadIdx.x] = a[threadIdx.x];
    __syncthreads();
    int k = threadIdx.x & 127;
    int cq = threadIdx.x >> 7;    // 0..7
    const float* base = W1 + (size_t)(h * 128) * 128;
    float sum = 0.f;
#pragma unroll
    for (int c = cq * 16; c < cq * 16 + 16; c++)
        sum += sa[c] * base[(size_t)c * 128 + k];    // coalesced across k
    part[cq][k] = sum;
    __syncthreads();
    if (cq == 0) {
        float t = part[0][k] + part[1][k] + part[2][k] + part[3][k]
                + part[4][k] + part[5][k] + part[6][k] + part[7][k];
        q[hp * 128 + k] = t;
    }
}

// ---------------- layer-1 s,d from x directly: warp per node ----------------
__global__ void k_sd1(const float* __restrict__ x, const float* __restrict__ q,
                      float* __restrict__ s, float* __restrict__ d, int nn) {
    __shared__ float sq[8][128];
    for (int i = threadIdx.x; i < 1024; i += blockDim.x) sq[i >> 7][i & 127] = q[i];
    __syncthreads();
    int node = (blockIdx.x * blockDim.x + threadIdx.x) >> 5;
    int lane = threadIdx.x & 31;
    if (node >= nn) return;
    float4 v = *(const float4*)(x + (size_t)node * 128 + lane * 4);
    float sum[8];
#pragma unroll
    for (int j = 0; j < 8; j++) {
        const float* qp = &sq[j][lane * 4];
        sum[j] = v.x * qp[0] + v.y * qp[1] + v.z * qp[2] + v.w * qp[3];
    }
#pragma unroll
    for (int j = 0; j < 8; j++)
#pragma unroll
        for (int o = 16; o; o >>= 1) sum[j] += __shfl_xor_sync(0xffffffffu, sum[j], o);
    if (lane == 0) {
        *(float4*)(s + node * 4) = make_float4(sum[0], sum[1], sum[2], sum[3]);
        *(float4*)(d + node * 4) = make_float4(sum[4], sum[5], sum[6], sum[7]);
    }
}

// ---------------- layer-1 aggregation in x-space: warp per node ----------------
__global__ void gat_agg_x(const float* __restrict__ x, const float* __restrict__ s,
                          const float* __restrict__ dvec,
                          const int* __restrict__ rp, const int* __restrict__ esrc,
                          float* __restrict__ aggx, int nn) {
    int node = (blockIdx.x * blockDim.x + threadIdx.x) >> 5;
    int lane = threadIdx.x & 31;
    if (node >= nn) return;
    float4 dv4 = *(const float4*)(dvec + node * 4);
    int beg = rp[node], end = rp[node + 1];
    float4 acc0 = make_float4(0.f, 0.f, 0.f, 0.f);
    float4 acc1 = acc0, acc2 = acc0, acc3 = acc0;
    float den0 = 0.f, den1 = 0.f, den2 = 0.f, den3 = 0.f;
#pragma unroll 2
    for (int i = beg; i < end; i++) {
        int sc = esrc[i];
        float4 sv = *(const float4*)(s + sc * 4);
        float e0 = sv.x + dv4.x; e0 = e0 > 0.f ? e0 : 0.2f * e0;
        float e1 = sv.y + dv4.y; e1 = e1 > 0.f ? e1 : 0.2f * e1;
        float e2 = sv.z + dv4.z; e2 = e2 > 0.f ? e2 : 0.2f * e2;
        float e3 = sv.w + dv4.w; e3 = e3 > 0.f ? e3 : 0.2f * e3;
        float w0 = __expf(e0), w1 = __expf(e1), w2 = __expf(e2), w3 = __expf(e3);
        den0 += w0; den1 += w1; den2 += w2; den3 += w3;
        float4 v = *(const float4*)(x + (size_t)sc * 128 + lane * 4);
        acc0.x += w0 * v.x; acc0.y += w0 * v.y; acc0.z += w0 * v.z; acc0.w += w0 * v.w;
        acc1.x += w1 * v.x; acc1.y += w1 * v.y; acc1.z += w1 * v.z; acc1.w += w1 * v.w;
        acc2.x += w2 * v.x; acc2.y += w2 * v.y; acc2.z += w2 * v.z; acc2.w += w2 * v.w;
        acc3.x += w3 * v.x; acc3.y += w3 * v.y; acc3.z += w3 * v.z; acc3.w += w3 * v.w;
    }
    float i0 = 1.f / den0, i1 = 1.f / den1, i2 = 1.f / den2, i3 = 1.f / den3;
    float* op = aggx + (size_t)node * 512 + lane * 4;
    *(float4*)(op + 0)   = make_float4(acc0.x * i0, acc0.y * i0, acc0.z * i0, acc0.w * i0);
    *(float4*)(op + 128) = make_float4(acc1.x * i1, acc1.y * i1, acc1.z * i1, acc1.w * i1);
    *(float4*)(op + 256) = make_float4(acc2.x * i2, acc2.y * i2, acc2.z * i2, acc2.w * i2);
    *(float4*)(op + 384) = make_float4(acc3.x * i3, acc3.y * i3, acc3.z * i3, acc3.w * i3);
}

// ---------------- TF32 tensor-core GEMM (double-buffered cp.async) ----------------
__device__ __forceinline__ void cpa16(void* dst, const void* src, int pred_bytes) {
    unsigned u = (unsigned)__cvta_generic_to_shared(dst);
    asm volatile("cp.async.cg.shared.global [%0], [%1], 16, %2;"
                 :: "r"(u), "l"(src), "r"(pred_bytes));
}

__global__ __launch_bounds__(256) void mma_nt(
    const float* __restrict__ A, const float* __restrict__ B,
    float* __restrict__ C, const float* __restrict__ bias,
    const float* __restrict__ as_, const float* __restrict__ ad_,
    float* __restrict__ sv, float* __restrict__ dvv,
    int M, int N, int K, int lda, int ldb, int ldc,
    int gA, int gB, int gC, int do_elu) {
    A += (size_t)blockIdx.z * gA;
    B += (size_t)blockIdx.z * gB;
    C += (size_t)blockIdx.z * gC;
    if (bias) bias += (size_t)blockIdx.z * N;
    __shared__ float As[2][128][36];
    __shared__ float Bs[2][128][36];
    const int t = threadIdx.x;
    const int lane = t & 31;
    const int wid = t >> 5;
    const int wm = (wid & 1) * 64;
    const int wn = (wid >> 1) * 32;
    const int group = lane >> 2, tig = lane & 3;
    const int bm = blockIdx.y * 128, bn = blockIdx.x * 128;
    const int lr = t >> 3;
    const int lc = (t & 7) * 4;

    float c[4][4][4];
#pragma unroll
    for (int i = 0; i < 4; i++)
#pragma unroll
        for (int j = 0; j < 4; j++)
#pragma unroll
            for (int q = 0; q < 4; q++) c[i][j][q] = 0.f;

    const int nsteps = K >> 5;

    auto load_stage = [&](int st, int kk) {
#pragma unroll
        for (int i = 0; i < 4; i++) {
            int m = lr + i * 32;
            int gm = bm + m;
            const float* asrc = A + (size_t)(gm < M ? gm : 0) * lda + kk + lc;
            cpa16(&As[st][m][lc], asrc, gm < M ? 16 : 0);
            int gn = bn + m;
            const float* bsrc = B + (size_t)(gn < N ? gn : 0) * ldb + kk + lc;
            cpa16(&Bs[st][m][lc], bsrc, gn < N ? 16 : 0);
        }
        asm volatile("cp.async.commit_group;");
    };

    load_stage(0, 0);

    for (int it = 0; it < nsteps; it++) {
        int st = it & 1;
        if (it + 1 < nsteps) {
            load_stage(st ^ 1, (it + 1) * 32);
            asm volatile("cp.async.wait_group 1;");
        } else {
            asm volatile("cp.async.wait_group 0;");
        }
        __syncthreads();
#pragma unroll
        for (int ks = 0; ks < 32; ks += 8) {
            unsigned bf[4][2];
#pragma unroll
            for (int nf = 0; nf < 4; nf++) {
                const float* bp = &Bs[st][wn + nf * 8 + group][ks + tig];
                bf[nf][0] = __float_as_uint(bp[0]);
                bf[nf][1] = __float_as_uint(bp[4]);
            }
#pragma unroll
            for (int mf = 0; mf < 4; mf++) {
                const float* ap0 = &As[st][wm + mf * 16 + group][ks + tig];
                const float* ap1 = &As[st][wm + mf * 16 + group + 8][ks + tig];
                unsigned a0 = __float_as_uint(ap0[0]);
                unsigned a1 = __float_as_uint(ap1[0]);
                unsigned a2 = __float_as_uint(ap0[4]);
                unsigned a3 = __float_as_uint(ap1[4]);
#pragma unroll
                for (int nf = 0; nf < 4; nf++) {
                    asm volatile(
                        "mma.sync.aligned.m16n8k8.row.col.f32.tf32.tf32.f32 "
                        "{%0,%1,%2,%3}, {%4,%5,%6,%7}, {%8,%9}, {%0,%1,%2,%3};"
                        : "+f"(c[mf][nf][0]), "+f"(c[mf][nf][1]),
                          "+f"(c[mf][nf][2]), "+f"(c[mf][nf][3])
                        : "r"(a0), "r"(a1), "r"(a2), "r"(a3),
                          "r"(bf[nf][0]), "r"(bf[nf][1]));
                }
            }
        }
        __syncthreads();
    }
    const int head = wn >> 5;
#pragma unroll
    for (int mf = 0; mf < 4; mf++) {
        int m0 = bm + wm + mf * 16 + group;
        int m1 = m0 + 8;
        float ps0 = 0.f, pd0 = 0.f, ps1 = 0.f, pd1 = 0.f;
#pragma unroll
        for (int nf = 0; nf < 4; nf++) {
            int n0 = bn + wn + nf * 8 + tig * 2;
            float v0 = c[mf][nf][0], v1 = c[mf][nf][1];
            float v2 = c[mf][nf][2], v3 = c[mf][nf][3];
            if (bias) {
                float b0 = bias[n0], b1v = bias[n0 + 1];
                v0 += b0; v1 += b1v; v2 += b0; v3 += b1v;
            }
            if (do_elu) {
                v0 = v0 > 0.f ? v0 : expm1f(v0);
                v1 = v1 > 0.f ? v1 : expm1f(v1);
                v2 = v2 > 0.f ? v2 : expm1f(v2);
                v3 = v3 > 0.f ? v3 : expm1f(v3);
            }
            if (sv) {
                int cl = head * 32 + nf * 8 + tig * 2;
                float a0 = as_[cl], a1v = as_[cl + 1];
                float d0 = ad_[cl], d1v = ad_[cl + 1];
                ps0 += v0 * a0 + v1 * a1v;
                pd0 += v0 * d0 + v1 * d1v;
                ps1 += v2 * a0 + v3 * a1v;
                pd1 += v2 * d0 + v3 * d1v;
            }
            if (m0 < M) *(float2*)(C + (size_t)m0 * ldc + n0) = make_float2(v0, v1);
            if (m1 < M) *(float2*)(C + (size_t)m1 * ldc + n0) = make_float2(v2, v3);
        }
        if (sv) {
            ps0 += __shfl_xor_sync(0xffffffffu, ps0, 1);
            ps0 += __shfl_xor_sync(0xffffffffu, ps0, 2);
            pd0 += __shfl_xor_sync(0xffffffffu, pd0, 1);
            pd0 += __shfl_xor_sync(0xffffffffu, pd0, 2);
            ps1 += __shfl_xor_sync(0xffffffffu, ps1, 1);
            ps1 += __shfl_xor_sync(0xffffffffu, ps1, 2);
            pd1 += __shfl_xor_sync(0xffffffffu, pd1, 1);
            pd1 += __shfl_xor_sync(0xffffffffu, pd1, 2);
            if (tig == 0) {
                if (m0 < M) { sv[m0 * 4 + head] = ps0; dvv[m0 * 4 + head] = pd0; }
                if (m1 < M) { sv[m1 * 4 + head] = ps1; dvv[m1 * 4 + head] = pd1; }
            }
        }
    }
}

// ---------------- layer-2 aggregation + fused layer-3 GEMM + logits ---------------
__global__ void gat_agg2_f(const float* __restrict__ h, const float* __restrict__ s,
                           const float* __restrict__ dvec, const float* __restrict__ bias,
                           const int* __restrict__ rp, const int* __restrict__ esrc,
                           const float* __restrict__ W3, const float* __restrict__ a3s,
                           const float* __restrict__ a3d,
                           float* __restrict__ h3out, float* __restrict__ s3,
                           float* __restrict__ d3, int nn) {
    __shared__ float sW3[8 * 128];
    __shared__ float sa3[8], sd3c[8], sb2[128];
    for (int i = threadIdx.x; i < 1024; i += blockDim.x) sW3[i] = W3[i];
    if (threadIdx.x < 8) { sa3[threadIdx.x] = a3s[threadIdx.x]; sd3c[threadIdx.x] = a3d[threadIdx.x]; }
    for (int i = threadIdx.x; i < 128; i += blockDim.x) sb2[i] = bias[i];
    __syncthreads();

    int node = (blockIdx.x * blockDim.x + threadIdx.x) >> 5;
    int lane = threadIdx.x & 31;
    if (node >= nn) return;
    int myh = lane >> 3;
    float dval = dvec[node * 4 + myh];
    int beg = rp[node], end = rp[node + 1];

    float acc[4] = {0.f, 0.f, 0.f, 0.f};
    float den = 0.f;
#pragma unroll 2
    for (int i = beg; i < end; i++) {
        int sc = esrc[i];
        float e = s[sc * 4 + myh] + dval;
        e = e > 0.f ? e : 0.2f * e;
        float w = __expf(e);
        den += w;
        float4 v = *(const float4*)(h + (size_t)sc * 128 + lane * 4);
        acc[0] += w * v.x; acc[1] += w * v.y; acc[2] += w * v.z; acc[3] += w * v.w;
    }
    float inv = 1.f / den;
    float v[4];
#pragma unroll
    for (int j = 0; j < 4; j++) {
        float t = acc[j] * inv + sb2[lane * 4 + j];
        v[j] = t > 0.f ? t : expm1f(t);
    }
    float p[8];
#pragma unroll
    for (int o = 0; o < 8; o++) {
        const float* w3 = &sW3[o * 128 + lane * 4];
        p[o] = v[0] * w3[0] + v[1] * w3[1] + v[2] * w3[2] + v[3] * w3[3];
    }
#pragma unroll
    for (int o = 0; o < 8; o++)
#pragma unroll
        for (int off = 16; off; off >>= 1) p[o] += __shfl_xor_sync(0xffffffffu, p[o], off);
    if (lane == 0) {
        float ss = 0.f, dd = 0.f;
#pragma unroll
        for (int o = 0; o < 8; o++) { ss += p[o] * sa3[o]; dd += p[o] * sd3c[o]; }
        *(float4*)(h3out + node * 8)     = make_float4(p[0], p[1], p[2], p[3]);
        *(float4*)(h3out + node * 8 + 4) = make_float4(p[4], p[5], p[6], p[7]);
        s3[node] = ss;
        d3[node] = dd;
    }
}

// ---------------- layer-3 aggregation ----------------
__global__ void gat_agg3(const float* __restrict__ h, const float* __restrict__ s,
                         const float* __restrict__ dv, const float* __restrict__ bias,
                         const int* __restrict__ rp, const int* __restrict__ esrc,
                         float* __restrict__ out, int nn) {
    int gwarp = (blockIdx.x * blockDim.x + threadIdx.x) >> 5;
    int lane = threadIdx.x & 31;
    int node = gwarp * 4 + lane / 8;
    if (node >= nn) return;
    int sub = lane & 7;
    float dval = dv[node];
    int beg = rp[node], end = rp[node + 1];
    float acc = 0.f, den = 0.f;
#pragma unroll 2
    for (int i = beg; i < end; i++) {
        int sc = esrc[i];
        float e = s[sc] + dval;
        e = e > 0.f ? e : 0.2f * e;
        float w = __expf(e);
        den += w;
        acc += w * h[sc * 8 + sub];
    }
    float vv = acc / den + bias[sub];
    out[node * 8 + sub] = vv > 0.f ? vv : expm1f(vv);
}

// ---------------- final edge MLP: 19 -> 16 -> 1 ----------------
__global__ void edge_mlp(const float* __restrict__ h3, const int* __restrict__ ei,
                         const float* __restrict__ ea, const float* __restrict__ yr,
                         const float* __restrict__ qt, const float* __restrict__ w1,
                         const float* __restrict__ b1, const float* __restrict__ w2,
                         const float* __restrict__ b2, float* __restrict__ out, int E) {
    __shared__ float sw1[16 * 19], sb1[16], sw2[16], sb2;
    for (int i = threadIdx.x; i < 16 * 19; i += blockDim.x) sw1[i] = w1[i];
    if (threadIdx.x < 16) { sb1[threadIdx.x] = b1[threadIdx.x]; sw2[threadIdx.x] = w2[threadIdx.x]; }
    if (threadIdx.x == 0) sb2 = b2[0];
    __syncthreads();
    int e = blockIdx.x * blockDim.x + threadIdx.x;
    if (e >= E) return;
    int si = ei[e], di = ei[E + e];
    float z[19];
#pragma unroll
    for (int j = 0; j < 8; j++) { z[j] = h3[si * 8 + j]; z[8 + j] = h3[di * 8 + j]; }
    z[16] = ea[e];
    z[17] = yr[e];
    z[18] = qt[e];
    float o = sb2;
#pragma unroll
    for (int j = 0; j < 16; j++) {
        float a = sb1[j];
#pragma unroll
        for (int i = 0; i < 19; i++) a += sw1[j * 19 + i] * z[i];
        o += sw2[j] * fmaxf(a, 0.f);
    }
    out[e] = o;
}

// ---------------- host ----------------
static void* sym_addr(const void* symbol) {
    void* p = nullptr;
    cudaGetSymbolAddress(&p, symbol);
    return p;
}

extern "C" void kernel_launch(void* const* d_in, const int* in_sizes, int n_in,
                              void* d_out, int out_size) {
    const float* x    = (const float*)d_in[0];
    const int*   ei   = (const int*)d_in[1];
    const float* ea   = (const float*)d_in[2];
    const float* yr   = (const float*)d_in[3];
    const float* qt   = (const float*)d_in[4];
    const float* W1   = (const float*)d_in[5];
    const float* a1s  = (const float*)d_in[6];
    const float* a1d  = (const float*)d_in[7];
    const float* b1   = (const float*)d_in[8];
    const float* W2   = (const float*)d_in[9];
    const float* a2s  = (const float*)d_in[10];
    const float* a2d  = (const float*)d_in[11];
    const float* b2   = (const float*)d_in[12];
    const float* W3   = (const float*)d_in[13];
    const float* a3s  = (const float*)d_in[14];
    const float* a3d  = (const float*)d_in[15];
    const float* b3   = (const float*)d_in[16];
    const float* f1w  = (const float*)d_in[17];
    const float* f1b  = (const float*)d_in[18];
    const float* f2w  = (const float*)d_in[19];
    const float* f2b  = (const float*)d_in[20];
    float* out = (float*)d_out;

    const int Nn = in_sizes[0] / 128;
    const int E  = in_sizes[1] / 2;

    float* aggx = (float*)sym_addr(g_h1);
    float* o1 = (float*)sym_addr(g_o1);
    float* h2 = (float*)sym_addr(g_h2);
    float* h3 = (float*)sym_addr(g_h3);
    float* o3 = (float*)sym_addr(g_o3);
    float* sv = (float*)sym_addr(g_s);
    float* dv = (float*)sym_addr(g_d);
    float* s3 = (float*)sym_addr(g_s3);
    float* d3 = (float*)sym_addr(g_d3);
    float* q  = (float*)sym_addr(g_q);
    int* counts = (int*)sym_addr(g_counts);
    int* rp     = (int*)sym_addr(g_rowptr);
    int* cur    = (int*)sym_addr(g_cursor);
    int* esrc   = (int*)sym_addr(g_esrc);

    const int TB = 128;

    // CSR (dst -> incoming src list); self-loop "+1" folded into the scan.
    cudaMemsetAsync(counts, 0, Nn * sizeof(int));
    k_count_edges<<<(E + TB - 1) / TB, TB>>>(ei, counts, E);
    k_scan<<<1, 1024>>>(counts, rp, cur, Nn);
    k_scatter<<<(E + Nn + TB - 1) / TB, TB>>>(ei, cur, esrc, E, Nn);

    // ---- layer 1: aggregate x (128-dim), then grouped GEMM to 4x128 with elu ----
    {
        k_proj<<<8, 1024>>>(W1, a1s, a1d, q);
        k_sd1<<<(Nn * 32 + 255) / 256, 256>>>(x, q, sv, dv, Nn);
        gat_agg_x<<<(Nn * 32 + TB - 1) / TB, TB>>>(x, sv, dv, rp, esrc, aggx, Nn);
        dim3 g(1, (Nn + 127) / 128, 4);
        mma_nt<<<g, 256>>>(aggx, W1, o1, b1, nullptr, nullptr, nullptr, nullptr,
                           Nn, 128, 128, 512, 128, 512, 128, 128 * 128, 128, 1);
    }
    // ---- layer 2 GEMM (512 -> 128) with fused s,d logits ----
    {
        dim3 g(1, (Nn + 127) / 128, 1);
        mma_nt<<<g, 256>>>(o1, W2, h2, nullptr, a2s, a2d, sv, dv,
                           Nn, 128, 512, 512, 512, 128, 0, 0, 0, 0);
    }
    // ---- layer 2 aggregation + fused layer-3 GEMM + layer-3 logits ----
    gat_agg2_f<<<(Nn * 32 + TB - 1) / TB, TB>>>(h2, sv, dv, b2, rp, esrc,
                                                W3, a3s, a3d, h3, s3, d3, Nn);
    // ---- layer 3 aggregation ----
    gat_agg3<<<(Nn * 8 + TB - 1) / TB, TB>>>(h3, s3, d3, b3, rp, esrc, o3, Nn);
    // ---- edge MLP ----
    edge_mlp<<<(E + TB - 1) / TB, TB>>>(o3, ei, ea, yr, qt, f1w, f1b, f2w, f2b, out, E);
}